// round 8
// baseline (speedup 1.0000x reference)
#include <cuda_runtime.h>
#include <cuda_bf16.h>
#include <cstdint>

// Problem constants
#define NN   50000
#define EE   800000
#define FIN  128
#define FHID 128
#define FOUT 64

// ---------------------------------------------------------------------------
// Scratch (static __device__ arrays — no allocation allowed)
// ---------------------------------------------------------------------------
__device__ float g_h[(size_t)NN * FHID];    // hs1 = (x@W1)*dis
__device__ float g_agg[(size_t)NN * FHID];  // h = relu(dis*(sum)+b1)
__device__ float g_h2[(size_t)NN * FOUT];   // hs2 = (h@W2)*dis
__device__ int   g_deg[NN];                 // in-degree histogram
__device__ float g_dis[NN];                 // (deg+1)^-1/2
__device__ int   g_starts[NN + 1];          // CSR row starts
__device__ int   g_cursor[NN];              // atomic fill cursors
__device__ int   g_csr_row[EE];             // source node per CSR slot
__device__ int   g_blocksum[64];            // per-block degree sums
// Pre-converted weights (hi/lo bf16 split), done ONCE instead of per GEMM block
__device__ __nv_bfloat16 g_w1hi[FIN * FHID];
__device__ __nv_bfloat16 g_w1lo[FIN * FHID];
__device__ __nv_bfloat16 g_w2hi[FHID * FOUT];
__device__ __nv_bfloat16 g_w2lo[FHID * FOUT];

// ---------------------------------------------------------------------------
// PTX helpers
// ---------------------------------------------------------------------------
__device__ __forceinline__ uint32_t smem_u32(const void* p) {
    return (uint32_t)__cvta_generic_to_shared(p);
}

__device__ __forceinline__ void ldmat_x4(uint32_t& r0, uint32_t& r1, uint32_t& r2, uint32_t& r3,
                                         uint32_t addr) {
    asm volatile("ldmatrix.sync.aligned.m8n8.x4.shared.b16 {%0,%1,%2,%3}, [%4];"
                 : "=r"(r0), "=r"(r1), "=r"(r2), "=r"(r3) : "r"(addr));
}
__device__ __forceinline__ void ldmat_x4_t(uint32_t& r0, uint32_t& r1, uint32_t& r2, uint32_t& r3,
                                           uint32_t addr) {
    asm volatile("ldmatrix.sync.aligned.m8n8.x4.trans.shared.b16 {%0,%1,%2,%3}, [%4];"
                 : "=r"(r0), "=r"(r1), "=r"(r2), "=r"(r3) : "r"(addr));
}

__device__ __forceinline__ void mma_bf16(float* d, const uint32_t* a, uint32_t b0, uint32_t b1) {
    asm volatile(
        "mma.sync.aligned.m16n8k16.row.col.f32.bf16.bf16.f32 "
        "{%0,%1,%2,%3}, {%4,%5,%6,%7}, {%8,%9}, {%0,%1,%2,%3};"
        : "+f"(d[0]), "+f"(d[1]), "+f"(d[2]), "+f"(d[3])
        : "r"(a[0]), "r"(a[1]), "r"(a[2]), "r"(a[3]), "r"(b0), "r"(b1));
}

// pack two fp32 into bf16x2 (hi) and residual bf16x2 (lo)
__device__ __forceinline__ void split2(float v0, float v1, uint32_t& hi, uint32_t& lo) {
    __nv_bfloat16 h0 = __float2bfloat16_rn(v0);
    __nv_bfloat16 h1 = __float2bfloat16_rn(v1);
    __nv_bfloat16 l0 = __float2bfloat16_rn(v0 - __bfloat162float(h0));
    __nv_bfloat16 l1 = __float2bfloat16_rn(v1 - __bfloat162float(h1));
    __nv_bfloat162 ph = {h0, h1}, pl = {l0, l1};
    hi = *(uint32_t*)&ph;
    lo = *(uint32_t*)&pl;
}

// ---------------------------------------------------------------------------
// One-shot W conversion: fp32 -> (hi, lo) bf16 for both weight matrices
// ---------------------------------------------------------------------------
__global__ void wconv_kernel(const float* __restrict__ W1, const float* __restrict__ W2,
                             __nv_bfloat16* __restrict__ w1hi, __nv_bfloat16* __restrict__ w1lo,
                             __nv_bfloat16* __restrict__ w2hi, __nv_bfloat16* __restrict__ w2lo) {
    constexpr int N1 = (FIN * FHID) / 2;    // float2 pairs in W1
    constexpr int N2 = (FHID * FOUT) / 2;   // float2 pairs in W2
    int i = blockIdx.x * blockDim.x + threadIdx.x;
    if (i < N1) {
        float2 v = *(const float2*)(W1 + (size_t)i * 2);
        uint32_t hi, lo;
        split2(v.x, v.y, hi, lo);
        *(uint32_t*)(w1hi + (size_t)i * 2) = hi;
        *(uint32_t*)(w1lo + (size_t)i * 2) = lo;
    } else if (i < N1 + N2) {
        int j = i - N1;
        float2 v = *(const float2*)(W2 + (size_t)j * 2);
        uint32_t hi, lo;
        split2(v.x, v.y, hi, lo);
        *(uint32_t*)(w2hi + (size_t)j * 2) = hi;
        *(uint32_t*)(w2lo + (size_t)j * 2) = lo;
    }
}

// ---------------------------------------------------------------------------
// Degree histogram (int4-vectorized: 4 edges per thread, 4x MLP on the REDs)
// ---------------------------------------------------------------------------
__global__ void count_deg_kernel(const int* __restrict__ col, int* __restrict__ deg, int e) {
    int i = blockIdx.x * blockDim.x + threadIdx.x;   // over e/4
    if (i * 4 + 3 < e) {
        int4 c = *(const int4*)(col + i * 4);
        atomicAdd(&deg[c.x], 1);
        atomicAdd(&deg[c.y], 1);
        atomicAdd(&deg[c.z], 1);
        atomicAdd(&deg[c.w], 1);
    } else {
        for (int j = i * 4; j < e; j++) atomicAdd(&deg[col[j]], 1);
    }
}

// ---------------------------------------------------------------------------
// scan1: per-block (1024 elems) degree totals; also computes dis = rsqrt(deg+1)
// ---------------------------------------------------------------------------
__global__ void __launch_bounds__(256)
scan1_kernel(const int* __restrict__ deg, int* __restrict__ blocksum,
             float* __restrict__ dis, int n) {
    __shared__ int wsum[8];
    int t = threadIdx.x, b = blockIdx.x;
    int base = b * 1024 + t * 4;
    int s = 0;
#pragma unroll
    for (int j = 0; j < 4; j++) {
        int idx = base + j;
        int d = (idx < n) ? deg[idx] : 0;
        s += d;
        if (idx < n) dis[idx] = rsqrtf((float)d + 1.0f);
    }
#pragma unroll
    for (int o = 16; o > 0; o >>= 1) s += __shfl_down_sync(0xffffffffu, s, o);
    if ((t & 31) == 0) wsum[t >> 5] = s;
    __syncthreads();
    if (t == 0) {
        int tot = 0;
#pragma unroll
        for (int w = 0; w < 8; w++) tot += wsum[w];
        blocksum[b] = tot;
    }
}

// ---------------------------------------------------------------------------
// scan3: per-block exclusive scan; block offset via parallel reduce of the
// (<=64) block sums.
// ---------------------------------------------------------------------------
__global__ void __launch_bounds__(256)
scan3_kernel(const int* __restrict__ deg, const int* __restrict__ blocksum,
             int* __restrict__ starts, int* __restrict__ cursor, int n, int nblk) {
    __shared__ int wtot[8];
    __shared__ int sh_off[2];
    __shared__ int sh_tot[2];
    int t = threadIdx.x, b = blockIdx.x;
    int lane = t & 31, wid = t >> 5;

    if (t < 64) {
        int v = (t < nblk) ? blocksum[t] : 0;
        int voff = (t < b) ? v : 0;
#pragma unroll
        for (int o = 16; o > 0; o >>= 1) {
            voff += __shfl_down_sync(0xffffffffu, voff, o);
            v    += __shfl_down_sync(0xffffffffu, v, o);
        }
        if (lane == 0) { sh_off[wid] = voff; sh_tot[wid] = v; }
    }

    int base = b * 1024 + t * 4;
    int v4[4];
#pragma unroll
    for (int j = 0; j < 4; j++) {
        int idx = base + j;
        v4[j] = (idx < n) ? deg[idx] : 0;
    }
    int tsum = v4[0] + v4[1] + v4[2] + v4[3];
    int incl = tsum;
#pragma unroll
    for (int o = 1; o < 32; o <<= 1) {
        int u = __shfl_up_sync(0xffffffffu, incl, o);
        if (lane >= o) incl += u;
    }
    if (lane == 31) wtot[wid] = incl;
    __syncthreads();

    int boff = sh_off[0] + sh_off[1];
    if (b == nblk - 1 && t == 0) starts[n] = sh_tot[0] + sh_tot[1];

    int woff = 0;
#pragma unroll
    for (int w = 0; w < 8; w++) woff += (w < wid) ? wtot[w] : 0;
    int excl = boff + woff + incl - tsum;
#pragma unroll
    for (int j = 0; j < 4; j++) {
        int idx = base + j;
        if (idx < n) { starts[idx] = excl; cursor[idx] = excl; }
        excl += v4[j];
    }
}

// CSR fill
__global__ void fill_kernel(const int* __restrict__ row, const int* __restrict__ col,
                            int* __restrict__ cursor, int* __restrict__ csr_row, int e) {
    int i = blockIdx.x * blockDim.x + threadIdx.x;
    if (i < e) {
        int slot = atomicAdd(&cursor[col[i]], 1);
        csr_row[slot] = row[i];
    }
}

// ---------------------------------------------------------------------------
// Tensor-core GEMM via split-bf16 (3xBF16 ~ fp32 precision):
//   out[N, F] = (x[N, 128] @ W[128, F]) * dis[row]
// W comes in pre-converted bf16 hi/lo (straight uint4 smem copies).
// BM=64, 8 warps (warp = 16-row slab x F/2 cols), 3 CTAs/SM.
// ---------------------------------------------------------------------------
template <int F>
__global__ void __launch_bounds__(256, 3)
gemm_tc_kernel(const float* __restrict__ x,
               const __nv_bfloat16* __restrict__ whi_g,
               const __nv_bfloat16* __restrict__ wlo_g,
               float* __restrict__ out, const float* __restrict__ dis, int nrows) {
    constexpr int BM   = 64;
    constexpr int KT   = 64;
    constexpr int NT   = F / 16;         // 8-col tiles per warp (covers F/2)
    constexpr int ASTR = KT + 8;         // 72
    constexpr int WSTR = F + 8;

    extern __shared__ __nv_bfloat16 smem[];
    __nv_bfloat16* Ahi = smem;                    // [BM][ASTR]
    __nv_bfloat16* Alo = Ahi + BM * ASTR;
    __nv_bfloat16* Whi = Alo + BM * ASTR;         // [KT][WSTR]
    __nv_bfloat16* Wlo = Whi + KT * WSTR;

    const int tid  = threadIdx.x;
    const int lane = tid & 31;
    const int w    = tid >> 5;           // warp 0..7
    const int slab = w >> 1;             // 16-row slab 0..3
    const int ch   = w & 1;              // column half
    const int row0 = blockIdx.x * BM;

    float acc[NT][4];
#pragma unroll
    for (int nt = 0; nt < NT; nt++)
#pragma unroll
        for (int j = 0; j < 4; j++) acc[nt][j] = 0.f;

    const int mat  = lane >> 3;
    const int mrow = lane & 7;

    for (int kt = 0; kt < FIN; kt += KT) {
        // ---- A tile: BM x KT fp32 -> hi/lo bf16 (converted here; rows used once) ----
        {
            constexpr int NV = (BM * KT) / 4;    // 1024
#pragma unroll
            for (int p = tid; p < NV; p += 256) {
                int r  = p / (KT / 4);
                int kq = (p % (KT / 4)) * 4;
                float4 v;
                int grow = row0 + r;
                if (grow < nrows)
                    v = *(const float4*)(x + (size_t)grow * FIN + kt + kq);
                else
                    v = make_float4(0.f, 0.f, 0.f, 0.f);
                uint32_t h01, l01, h23, l23;
                split2(v.x, v.y, h01, l01);
                split2(v.z, v.w, h23, l23);
                *(uint32_t*)(Ahi + r * ASTR + kq)     = h01;
                *(uint32_t*)(Ahi + r * ASTR + kq + 2) = h23;
                *(uint32_t*)(Alo + r * ASTR + kq)     = l01;
                *(uint32_t*)(Alo + r * ASTR + kq + 2) = l23;
            }
        }
        // ---- W tile: straight bf16 copy (8 bf16 per uint4) ----
        {
            constexpr int NV = (KT * F) / 8;
#pragma unroll
            for (int p = tid; p < NV; p += 256) {
                int k = p / (F / 8);
                int c = (p % (F / 8)) * 8;
                *(uint4*)(Whi + k * WSTR + c) = *(const uint4*)(whi_g + (size_t)(kt + k) * F + c);
                *(uint4*)(Wlo + k * WSTR + c) = *(const uint4*)(wlo_g + (size_t)(kt + k) * F + c);
            }
        }
        __syncthreads();

#pragma unroll
        for (int ks = 0; ks < KT / 16; ks++) {
            uint32_t ah[4], al[4];
            {
                int arow = slab * 16 + (mat & 1) * 8 + mrow;
                int acol = ks * 16 + (mat >> 1) * 8;
                uint32_t a_hi = smem_u32(Ahi + arow * ASTR + acol);
                uint32_t a_lo = smem_u32(Alo + arow * ASTR + acol);
                ldmat_x4(ah[0], ah[1], ah[2], ah[3], a_hi);
                ldmat_x4(al[0], al[1], al[2], al[3], a_lo);
            }
#pragma unroll
            for (int nt2 = 0; nt2 < NT / 2; nt2++) {
                int krow = ks * 16 + (mat & 1) * 8 + mrow;
                int ncol = ch * (F / 2) + nt2 * 16 + (mat >> 1) * 8;
                uint32_t w_hi = smem_u32(Whi + krow * WSTR + ncol);
                uint32_t w_lo = smem_u32(Wlo + krow * WSTR + ncol);
                uint32_t bh[4], bl[4];
                ldmat_x4_t(bh[0], bh[1], bh[2], bh[3], w_hi);
                ldmat_x4_t(bl[0], bl[1], bl[2], bl[3], w_lo);
                mma_bf16(acc[2 * nt2], ah, bh[0], bh[1]);
                mma_bf16(acc[2 * nt2], ah, bl[0], bl[1]);
                mma_bf16(acc[2 * nt2], al, bh[0], bh[1]);
                mma_bf16(acc[2 * nt2 + 1], ah, bh[2], bh[3]);
                mma_bf16(acc[2 * nt2 + 1], ah, bl[2], bl[3]);
                mma_bf16(acc[2 * nt2 + 1], al, bh[2], bh[3]);
            }
        }
        __syncthreads();
    }

    // ---- epilogue: scale by dis[row], write f32 ----
    {
        int r0 = row0 + slab * 16 + (lane >> 2);
        int r1 = r0 + 8;
        float s0 = (r0 < nrows) ? __ldg(dis + r0) : 0.f;
        float s1 = (r1 < nrows) ? __ldg(dis + r1) : 0.f;
        int cbase = ch * (F / 2) + (lane & 3) * 2;
#pragma unroll
        for (int nt = 0; nt < NT; nt++) {
            int c = cbase + nt * 8;
            if (r0 < nrows)
                *(float2*)(out + (size_t)r0 * F + c) = make_float2(acc[nt][0] * s0, acc[nt][1] * s0);
            if (r1 < nrows)
                *(float2*)(out + (size_t)r1 * F + c) = make_float2(acc[nt][2] * s1, acc[nt][3] * s1);
        }
    }
}

// ---------------------------------------------------------------------------
// CSR segment-sum aggregate (hs already scaled by dis[row]); 4-way ILP:
//   out[c] = act( dis[c] * ( hs[c] + sum_e hs[row_e] ) + bias )
// ---------------------------------------------------------------------------
template <int F, bool RELU>
__global__ void __launch_bounds__(256)
aggregate_kernel(const float* __restrict__ hs,
                 const int* __restrict__ csr_row, const int* __restrict__ starts,
                 const float* __restrict__ dis, const float* __restrict__ bias,
                 float* __restrict__ out, int n) {
    constexpr int LPN = F / 4;
    const int gtid = blockIdx.x * blockDim.x + threadIdx.x;
    const int node = gtid / LPN;
    const int sub  = gtid % LPN;
    if (node >= n) return;

    const int beg = __ldg(starts + node);
    const int end = __ldg(starts + node + 1);

    float4 a0 = *(const float4*)(hs + (size_t)node * F + sub * 4);  // self loop
    float4 a1 = make_float4(0.f, 0.f, 0.f, 0.f);
    float4 a2 = make_float4(0.f, 0.f, 0.f, 0.f);
    float4 a3 = make_float4(0.f, 0.f, 0.f, 0.f);

    int e = beg;
    for (; e + 3 < end; e += 4) {
        int r0 = __ldg(csr_row + e);
        int r1 = __ldg(csr_row + e + 1);
        int r2 = __ldg(csr_row + e + 2);
        int r3 = __ldg(csr_row + e + 3);
        float4 v0 = *(const float4*)(hs + (size_t)r0 * F + sub * 4);
        float4 v1 = *(const float4*)(hs + (size_t)r1 * F + sub * 4);
        float4 v2 = *(const float4*)(hs + (size_t)r2 * F + sub * 4);
        float4 v3 = *(const float4*)(hs + (size_t)r3 * F + sub * 4);
        a0.x += v0.x; a0.y += v0.y; a0.z += v0.z; a0.w += v0.w;
        a1.x += v1.x; a1.y += v1.y; a1.z += v1.z; a1.w += v1.w;
        a2.x += v2.x; a2.y += v2.y; a2.z += v2.z; a2.w += v2.w;
        a3.x += v3.x; a3.y += v3.y; a3.z += v3.z; a3.w += v3.w;
    }
    for (; e < end; e++) {
        int r0 = __ldg(csr_row + e);
        float4 v0 = *(const float4*)(hs + (size_t)r0 * F + sub * 4);
        a0.x += v0.x; a0.y += v0.y; a0.z += v0.z; a0.w += v0.w;
    }

    const float d = __ldg(dis + node);
    float4 bv = *(const float4*)(bias + sub * 4);
    float4 o;
    o.x = (a0.x + a1.x + a2.x + a3.x) * d + bv.x;
    o.y = (a0.y + a1.y + a2.y + a3.y) * d + bv.y;
    o.z = (a0.z + a1.z + a2.z + a3.z) * d + bv.z;
    o.w = (a0.w + a1.w + a2.w + a3.w) * d + bv.w;
    if (RELU) {
        o.x = fmaxf(o.x, 0.f); o.y = fmaxf(o.y, 0.f);
        o.z = fmaxf(o.z, 0.f); o.w = fmaxf(o.w, 0.f);
    }
    *(float4*)(out + (size_t)node * F + sub * 4) = o;
}

// ---------------------------------------------------------------------------
// Launch (single stream, sequential)
// ---------------------------------------------------------------------------
extern "C" void kernel_launch(void* const* d_in, const int* in_sizes, int n_in,
                              void* d_out, int out_size) {
    const float* x  = (const float*)d_in[0];
    const int*   ei = (const int*)d_in[1];
    const float* W1 = (const float*)d_in[2];
    const float* b1 = (const float*)d_in[3];
    const float* W2 = (const float*)d_in[4];
    const float* b2 = (const float*)d_in[5];
    float* out = (float*)d_out;

    const int* row = ei;
    const int* col = ei + EE;

    constexpr int SMEM1 = (64 * 72 * 2 + 64 * 136 * 2) * 2;  // 53,248 B (F=128)
    constexpr int SMEM2 = (64 * 72 * 2 + 64 * 72 * 2) * 2;   // 36,864 B (F=64)

    static float *p_h = nullptr, *p_agg = nullptr, *p_h2 = nullptr, *p_dis = nullptr;
    static int *p_deg = nullptr, *p_starts = nullptr, *p_cursor = nullptr,
               *p_csr = nullptr, *p_bsum = nullptr;
    static __nv_bfloat16 *p_w1hi = nullptr, *p_w1lo = nullptr, *p_w2hi = nullptr, *p_w2lo = nullptr;
    if (!p_h) {
        cudaGetSymbolAddress((void**)&p_h,      g_h);
        cudaGetSymbolAddress((void**)&p_agg,    g_agg);
        cudaGetSymbolAddress((void**)&p_h2,     g_h2);
        cudaGetSymbolAddress((void**)&p_dis,    g_dis);
        cudaGetSymbolAddress((void**)&p_deg,    g_deg);
        cudaGetSymbolAddress((void**)&p_starts, g_starts);
        cudaGetSymbolAddress((void**)&p_cursor, g_cursor);
        cudaGetSymbolAddress((void**)&p_csr,    g_csr_row);
        cudaGetSymbolAddress((void**)&p_bsum,   g_blocksum);
        cudaGetSymbolAddress((void**)&p_w1hi,   g_w1hi);
        cudaGetSymbolAddress((void**)&p_w1lo,   g_w1lo);
        cudaGetSymbolAddress((void**)&p_w2hi,   g_w2hi);
        cudaGetSymbolAddress((void**)&p_w2lo,   g_w2lo);
        cudaFuncSetAttribute(gemm_tc_kernel<128>,
                             cudaFuncAttributeMaxDynamicSharedMemorySize, SMEM1);
        cudaFuncSetAttribute(gemm_tc_kernel<64>,
                             cudaFuncAttributeMaxDynamicSharedMemorySize, SMEM2);
    }

    const int NBLK = (NN + 1023) / 1024;   // 49
    const int GBLK = (NN + 63) / 64;       // 782

    // ---- one-shot W conversion ----
    {
        constexpr int NPAIR = (FIN * FHID + FHID * FOUT) / 2;   // 12288
        wconv_kernel<<<(NPAIR + 255) / 256, 256>>>(W1, W2, p_w1hi, p_w1lo, p_w2hi, p_w2lo);
    }

    // ---- degree + dis + CSR build ----
    cudaMemsetAsync(p_deg, 0, (size_t)NN * sizeof(int), 0);
    count_deg_kernel<<<(EE / 4 + 255) / 256, 256>>>(col, p_deg, EE);
    scan1_kernel<<<NBLK, 256>>>(p_deg, p_bsum, p_dis, NN);
    scan3_kernel<<<NBLK, 256>>>(p_deg, p_bsum, p_starts, p_cursor, NN, NBLK);
    fill_kernel<<<(EE + 255) / 256, 256>>>(row, col, p_cursor, p_csr, EE);

    // ---- layer 1: tensor GEMM (hs1 = (x@W1)*dis) ----
    gemm_tc_kernel<128><<<GBLK, 256, SMEM1>>>(x, p_w1hi, p_w1lo, p_h, p_dis, NN);

    // ---- layer 1 aggregate -> g_agg = h ----
    {
        long long threads = (long long)NN * 32;
        aggregate_kernel<128, true><<<(int)((threads + 255) / 256), 256>>>(
            p_h, p_csr, p_starts, p_dis, b1, p_agg, NN);
    }

    // ---- layer 2: tensor GEMM (hs2 = (h@W2)*dis) ----
    gemm_tc_kernel<64><<<GBLK, 256, SMEM2>>>(p_agg, p_w2hi, p_w2lo, p_h2, p_dis, NN);

    // ---- layer 2 aggregate -> d_out ----
    {
        long long threads = (long long)NN * 16;
        aggregate_kernel<64, false><<<(int)((threads + 255) / 256), 256>>>(
            p_h2, p_csr, p_starts, p_dis, b2, out, NN);
    }
}

// round 9
// speedup vs baseline: 1.0006x; 1.0006x over previous
#include <cuda_runtime.h>
#include <cuda_bf16.h>
#include <cstdint>

// Problem constants
#define NN   50000
#define EE   800000
#define FIN  128
#define FHID 128
#define FOUT 64

// ---------------------------------------------------------------------------
// Scratch (static __device__ arrays — no allocation allowed)
// ---------------------------------------------------------------------------
__device__ float g_h[(size_t)NN * FHID];    // hs1 = (x@W1)*dis
__device__ float g_agg[(size_t)NN * FHID];  // h = relu(dis*(sum)+b1)
__device__ float g_h2[(size_t)NN * FOUT];   // hs2 = (h@W2)*dis
__device__ int   g_deg[NN];                 // in-degree histogram
__device__ float g_dis[NN];                 // (deg+1)^-1/2
__device__ int   g_starts[NN];              // CSR segment start per node (unordered ranges)
__device__ int   g_cursor[NN];              // atomic fill cursors
__device__ int   g_csr_row[EE];             // source node per CSR slot
__device__ int   g_total;                   // global range allocator
// Pre-converted weights (hi/lo bf16 split)
__device__ __nv_bfloat16 g_w1hi[FIN * FHID];
__device__ __nv_bfloat16 g_w1lo[FIN * FHID];
__device__ __nv_bfloat16 g_w2hi[FHID * FOUT];
__device__ __nv_bfloat16 g_w2lo[FHID * FOUT];

// ---------------------------------------------------------------------------
// PTX helpers
// ---------------------------------------------------------------------------
__device__ __forceinline__ uint32_t smem_u32(const void* p) {
    return (uint32_t)__cvta_generic_to_shared(p);
}

__device__ __forceinline__ void ldmat_x4(uint32_t& r0, uint32_t& r1, uint32_t& r2, uint32_t& r3,
                                         uint32_t addr) {
    asm volatile("ldmatrix.sync.aligned.m8n8.x4.shared.b16 {%0,%1,%2,%3}, [%4];"
                 : "=r"(r0), "=r"(r1), "=r"(r2), "=r"(r3) : "r"(addr));
}
__device__ __forceinline__ void ldmat_x4_t(uint32_t& r0, uint32_t& r1, uint32_t& r2, uint32_t& r3,
                                           uint32_t addr) {
    asm volatile("ldmatrix.sync.aligned.m8n8.x4.trans.shared.b16 {%0,%1,%2,%3}, [%4];"
                 : "=r"(r0), "=r"(r1), "=r"(r2), "=r"(r3) : "r"(addr));
}

__device__ __forceinline__ void mma_bf16(float* d, const uint32_t* a, uint32_t b0, uint32_t b1) {
    asm volatile(
        "mma.sync.aligned.m16n8k16.row.col.f32.bf16.bf16.f32 "
        "{%0,%1,%2,%3}, {%4,%5,%6,%7}, {%8,%9}, {%0,%1,%2,%3};"
        : "+f"(d[0]), "+f"(d[1]), "+f"(d[2]), "+f"(d[3])
        : "r"(a[0]), "r"(a[1]), "r"(a[2]), "r"(a[3]), "r"(b0), "r"(b1));
}

// pack two fp32 into bf16x2 (hi) and residual bf16x2 (lo)
__device__ __forceinline__ void split2(float v0, float v1, uint32_t& hi, uint32_t& lo) {
    __nv_bfloat16 h0 = __float2bfloat16_rn(v0);
    __nv_bfloat16 h1 = __float2bfloat16_rn(v1);
    __nv_bfloat16 l0 = __float2bfloat16_rn(v0 - __bfloat162float(h0));
    __nv_bfloat16 l1 = __float2bfloat16_rn(v1 - __bfloat162float(h1));
    __nv_bfloat162 ph = {h0, h1}, pl = {l0, l1};
    hi = *(uint32_t*)&ph;
    lo = *(uint32_t*)&pl;
}

// ---------------------------------------------------------------------------
// One-shot W conversion; also zeroes the range allocator
// ---------------------------------------------------------------------------
__global__ void wconv_kernel(const float* __restrict__ W1, const float* __restrict__ W2,
                             __nv_bfloat16* __restrict__ w1hi, __nv_bfloat16* __restrict__ w1lo,
                             __nv_bfloat16* __restrict__ w2hi, __nv_bfloat16* __restrict__ w2lo,
                             int* __restrict__ total) {
    constexpr int N1 = (FIN * FHID) / 2;
    constexpr int N2 = (FHID * FOUT) / 2;
    int i = blockIdx.x * blockDim.x + threadIdx.x;
    if (i == 0) *total = 0;
    if (i < N1) {
        float2 v = *(const float2*)(W1 + (size_t)i * 2);
        uint32_t hi, lo;
        split2(v.x, v.y, hi, lo);
        *(uint32_t*)(w1hi + (size_t)i * 2) = hi;
        *(uint32_t*)(w1lo + (size_t)i * 2) = lo;
    } else if (i < N1 + N2) {
        int j = i - N1;
        float2 v = *(const float2*)(W2 + (size_t)j * 2);
        uint32_t hi, lo;
        split2(v.x, v.y, hi, lo);
        *(uint32_t*)(w2hi + (size_t)j * 2) = hi;
        *(uint32_t*)(w2lo + (size_t)j * 2) = lo;
    }
}

// ---------------------------------------------------------------------------
// Degree histogram (int4-vectorized)
// ---------------------------------------------------------------------------
__global__ void count_deg_kernel(const int* __restrict__ col, int* __restrict__ deg, int e) {
    int i = blockIdx.x * blockDim.x + threadIdx.x;
    if (i * 4 + 3 < e) {
        int4 c = *(const int4*)(col + i * 4);
        atomicAdd(&deg[c.x], 1);
        atomicAdd(&deg[c.y], 1);
        atomicAdd(&deg[c.z], 1);
        atomicAdd(&deg[c.w], 1);
    } else {
        for (int j = i * 4; j < e; j++) atomicAdd(&deg[col[j]], 1);
    }
}

// ---------------------------------------------------------------------------
// alloc: unordered CSR range allocation via warp-aggregated atomicAdd.
// Segment ranges need NOT be in node order — each node just needs a
// contiguous range of size deg[node]. Replaces the entire prefix scan.
// Also computes dis = rsqrt(deg + 1).
// ---------------------------------------------------------------------------
__global__ void __launch_bounds__(256)
alloc_kernel(const int* __restrict__ deg, int* __restrict__ starts,
             int* __restrict__ cursor, float* __restrict__ dis,
             int* __restrict__ total, int n) {
    int i = blockIdx.x * blockDim.x + threadIdx.x;
    int lane = threadIdx.x & 31;
    int d = (i < n) ? deg[i] : 0;

    // warp inclusive scan of d
    int incl = d;
#pragma unroll
    for (int o = 1; o < 32; o <<= 1) {
        int u = __shfl_up_sync(0xffffffffu, incl, o);
        if (lane >= o) incl += u;
    }
    int wtot = __shfl_sync(0xffffffffu, incl, 31);
    int base = 0;
    if (lane == 31 && wtot > 0) base = atomicAdd(total, wtot);
    base = __shfl_sync(0xffffffffu, base, 31);

    if (i < n) {
        int s = base + incl - d;
        starts[i] = s;
        cursor[i] = s;
        dis[i] = rsqrtf((float)d + 1.0f);
    }
}

// ---------------------------------------------------------------------------
// CSR fill (int4-vectorized: 4 independent atomic+scatter chains per thread)
// ---------------------------------------------------------------------------
__global__ void fill_kernel(const int* __restrict__ row, const int* __restrict__ col,
                            int* __restrict__ cursor, int* __restrict__ csr_row, int e) {
    int i = blockIdx.x * blockDim.x + threadIdx.x;
    if (i * 4 + 3 < e) {
        int4 c = *(const int4*)(col + i * 4);
        int4 r = *(const int4*)(row + i * 4);
        int s0 = atomicAdd(&cursor[c.x], 1);
        int s1 = atomicAdd(&cursor[c.y], 1);
        int s2 = atomicAdd(&cursor[c.z], 1);
        int s3 = atomicAdd(&cursor[c.w], 1);
        csr_row[s0] = r.x;
        csr_row[s1] = r.y;
        csr_row[s2] = r.z;
        csr_row[s3] = r.w;
    } else {
        for (int j = i * 4; j < e; j++) {
            int slot = atomicAdd(&cursor[col[j]], 1);
            csr_row[slot] = row[j];
        }
    }
}

// ---------------------------------------------------------------------------
// Tensor-core GEMM via split-bf16 (3xBF16 ~ fp32 precision):
//   out[N, F] = (x[N, 128] @ W[128, F]) * dis[row]
// W pre-converted bf16 hi/lo. BM=64, 8 warps, 3 CTAs/SM.
// ---------------------------------------------------------------------------
template <int F>
__global__ void __launch_bounds__(256, 3)
gemm_tc_kernel(const float* __restrict__ x,
               const __nv_bfloat16* __restrict__ whi_g,
               const __nv_bfloat16* __restrict__ wlo_g,
               float* __restrict__ out, const float* __restrict__ dis, int nrows) {
    constexpr int BM   = 64;
    constexpr int KT   = 64;
    constexpr int NT   = F / 16;
    constexpr int ASTR = KT + 8;
    constexpr int WSTR = F + 8;

    extern __shared__ __nv_bfloat16 smem[];
    __nv_bfloat16* Ahi = smem;
    __nv_bfloat16* Alo = Ahi + BM * ASTR;
    __nv_bfloat16* Whi = Alo + BM * ASTR;
    __nv_bfloat16* Wlo = Whi + KT * WSTR;

    const int tid  = threadIdx.x;
    const int lane = tid & 31;
    const int w    = tid >> 5;
    const int slab = w >> 1;
    const int ch   = w & 1;
    const int row0 = blockIdx.x * BM;

    float acc[NT][4];
#pragma unroll
    for (int nt = 0; nt < NT; nt++)
#pragma unroll
        for (int j = 0; j < 4; j++) acc[nt][j] = 0.f;

    const int mat  = lane >> 3;
    const int mrow = lane & 7;

    for (int kt = 0; kt < FIN; kt += KT) {
        {
            constexpr int NV = (BM * KT) / 4;
#pragma unroll
            for (int p = tid; p < NV; p += 256) {
                int r  = p / (KT / 4);
                int kq = (p % (KT / 4)) * 4;
                float4 v;
                int grow = row0 + r;
                if (grow < nrows)
                    v = *(const float4*)(x + (size_t)grow * FIN + kt + kq);
                else
                    v = make_float4(0.f, 0.f, 0.f, 0.f);
                uint32_t h01, l01, h23, l23;
                split2(v.x, v.y, h01, l01);
                split2(v.z, v.w, h23, l23);
                *(uint32_t*)(Ahi + r * ASTR + kq)     = h01;
                *(uint32_t*)(Ahi + r * ASTR + kq + 2) = h23;
                *(uint32_t*)(Alo + r * ASTR + kq)     = l01;
                *(uint32_t*)(Alo + r * ASTR + kq + 2) = l23;
            }
        }
        {
            constexpr int NV = (KT * F) / 8;
#pragma unroll
            for (int p = tid; p < NV; p += 256) {
                int k = p / (F / 8);
                int c = (p % (F / 8)) * 8;
                *(uint4*)(Whi + k * WSTR + c) = *(const uint4*)(whi_g + (size_t)(kt + k) * F + c);
                *(uint4*)(Wlo + k * WSTR + c) = *(const uint4*)(wlo_g + (size_t)(kt + k) * F + c);
            }
        }
        __syncthreads();

#pragma unroll
        for (int ks = 0; ks < KT / 16; ks++) {
            uint32_t ah[4], al[4];
            {
                int arow = slab * 16 + (mat & 1) * 8 + mrow;
                int acol = ks * 16 + (mat >> 1) * 8;
                uint32_t a_hi = smem_u32(Ahi + arow * ASTR + acol);
                uint32_t a_lo = smem_u32(Alo + arow * ASTR + acol);
                ldmat_x4(ah[0], ah[1], ah[2], ah[3], a_hi);
                ldmat_x4(al[0], al[1], al[2], al[3], a_lo);
            }
#pragma unroll
            for (int nt2 = 0; nt2 < NT / 2; nt2++) {
                int krow = ks * 16 + (mat & 1) * 8 + mrow;
                int ncol = ch * (F / 2) + nt2 * 16 + (mat >> 1) * 8;
                uint32_t w_hi = smem_u32(Whi + krow * WSTR + ncol);
                uint32_t w_lo = smem_u32(Wlo + krow * WSTR + ncol);
                uint32_t bh[4], bl[4];
                ldmat_x4_t(bh[0], bh[1], bh[2], bh[3], w_hi);
                ldmat_x4_t(bl[0], bl[1], bl[2], bl[3], w_lo);
                mma_bf16(acc[2 * nt2], ah, bh[0], bh[1]);
                mma_bf16(acc[2 * nt2], ah, bl[0], bl[1]);
                mma_bf16(acc[2 * nt2], al, bh[0], bh[1]);
                mma_bf16(acc[2 * nt2 + 1], ah, bh[2], bh[3]);
                mma_bf16(acc[2 * nt2 + 1], ah, bl[2], bl[3]);
                mma_bf16(acc[2 * nt2 + 1], al, bh[2], bh[3]);
            }
        }
        __syncthreads();
    }

    {
        int r0 = row0 + slab * 16 + (lane >> 2);
        int r1 = r0 + 8;
        float s0 = (r0 < nrows) ? __ldg(dis + r0) : 0.f;
        float s1 = (r1 < nrows) ? __ldg(dis + r1) : 0.f;
        int cbase = ch * (F / 2) + (lane & 3) * 2;
#pragma unroll
        for (int nt = 0; nt < NT; nt++) {
            int c = cbase + nt * 8;
            if (r0 < nrows)
                *(float2*)(out + (size_t)r0 * F + c) = make_float2(acc[nt][0] * s0, acc[nt][1] * s0);
            if (r1 < nrows)
                *(float2*)(out + (size_t)r1 * F + c) = make_float2(acc[nt][2] * s1, acc[nt][3] * s1);
        }
    }
}

// ---------------------------------------------------------------------------
// CSR segment-sum aggregate; segment = [starts[node], starts[node]+deg[node])
// (ranges are unordered across nodes — allocated by atomics)
// ---------------------------------------------------------------------------
template <int F, bool RELU>
__global__ void __launch_bounds__(256)
aggregate_kernel(const float* __restrict__ hs,
                 const int* __restrict__ csr_row, const int* __restrict__ starts,
                 const int* __restrict__ deg,
                 const float* __restrict__ dis, const float* __restrict__ bias,
                 float* __restrict__ out, int n) {
    constexpr int LPN = F / 4;
    const int gtid = blockIdx.x * blockDim.x + threadIdx.x;
    const int node = gtid / LPN;
    const int sub  = gtid % LPN;
    if (node >= n) return;

    const int beg = __ldg(starts + node);
    const int end = beg + __ldg(deg + node);

    float4 a0 = *(const float4*)(hs + (size_t)node * F + sub * 4);  // self loop
    float4 a1 = make_float4(0.f, 0.f, 0.f, 0.f);
    float4 a2 = make_float4(0.f, 0.f, 0.f, 0.f);
    float4 a3 = make_float4(0.f, 0.f, 0.f, 0.f);

    int e = beg;
    for (; e + 3 < end; e += 4) {
        int r0 = __ldg(csr_row + e);
        int r1 = __ldg(csr_row + e + 1);
        int r2 = __ldg(csr_row + e + 2);
        int r3 = __ldg(csr_row + e + 3);
        float4 v0 = *(const float4*)(hs + (size_t)r0 * F + sub * 4);
        float4 v1 = *(const float4*)(hs + (size_t)r1 * F + sub * 4);
        float4 v2 = *(const float4*)(hs + (size_t)r2 * F + sub * 4);
        float4 v3 = *(const float4*)(hs + (size_t)r3 * F + sub * 4);
        a0.x += v0.x; a0.y += v0.y; a0.z += v0.z; a0.w += v0.w;
        a1.x += v1.x; a1.y += v1.y; a1.z += v1.z; a1.w += v1.w;
        a2.x += v2.x; a2.y += v2.y; a2.z += v2.z; a2.w += v2.w;
        a3.x += v3.x; a3.y += v3.y; a3.z += v3.z; a3.w += v3.w;
    }
    for (; e < end; e++) {
        int r0 = __ldg(csr_row + e);
        float4 v0 = *(const float4*)(hs + (size_t)r0 * F + sub * 4);
        a0.x += v0.x; a0.y += v0.y; a0.z += v0.z; a0.w += v0.w;
    }

    const float d = __ldg(dis + node);
    float4 bv = *(const float4*)(bias + sub * 4);
    float4 o;
    o.x = (a0.x + a1.x + a2.x + a3.x) * d + bv.x;
    o.y = (a0.y + a1.y + a2.y + a3.y) * d + bv.y;
    o.z = (a0.z + a1.z + a2.z + a3.z) * d + bv.z;
    o.w = (a0.w + a1.w + a2.w + a3.w) * d + bv.w;
    if (RELU) {
        o.x = fmaxf(o.x, 0.f); o.y = fmaxf(o.y, 0.f);
        o.z = fmaxf(o.z, 0.f); o.w = fmaxf(o.w, 0.f);
    }
    *(float4*)(out + (size_t)node * F + sub * 4) = o;
}

// ---------------------------------------------------------------------------
// Launch (single stream, sequential)
// ---------------------------------------------------------------------------
extern "C" void kernel_launch(void* const* d_in, const int* in_sizes, int n_in,
                              void* d_out, int out_size) {
    const float* x  = (const float*)d_in[0];
    const int*   ei = (const int*)d_in[1];
    const float* W1 = (const float*)d_in[2];
    const float* b1 = (const float*)d_in[3];
    const float* W2 = (const float*)d_in[4];
    const float* b2 = (const float*)d_in[5];
    float* out = (float*)d_out;

    const int* row = ei;
    const int* col = ei + EE;

    constexpr int SMEM1 = (64 * 72 * 2 + 64 * 136 * 2) * 2;  // 53,248 B (F=128)
    constexpr int SMEM2 = (64 * 72 * 2 + 64 * 72 * 2) * 2;   // 36,864 B (F=64)

    static float *p_h = nullptr, *p_agg = nullptr, *p_h2 = nullptr, *p_dis = nullptr;
    static int *p_deg = nullptr, *p_starts = nullptr, *p_cursor = nullptr,
               *p_csr = nullptr, *p_total = nullptr;
    static __nv_bfloat16 *p_w1hi = nullptr, *p_w1lo = nullptr, *p_w2hi = nullptr, *p_w2lo = nullptr;
    if (!p_h) {
        cudaGetSymbolAddress((void**)&p_h,      g_h);
        cudaGetSymbolAddress((void**)&p_agg,    g_agg);
        cudaGetSymbolAddress((void**)&p_h2,     g_h2);
        cudaGetSymbolAddress((void**)&p_dis,    g_dis);
        cudaGetSymbolAddress((void**)&p_deg,    g_deg);
        cudaGetSymbolAddress((void**)&p_starts, g_starts);
        cudaGetSymbolAddress((void**)&p_cursor, g_cursor);
        cudaGetSymbolAddress((void**)&p_csr,    g_csr_row);
        cudaGetSymbolAddress((void**)&p_total,  g_total);
        cudaGetSymbolAddress((void**)&p_w1hi,   g_w1hi);
        cudaGetSymbolAddress((void**)&p_w1lo,   g_w1lo);
        cudaGetSymbolAddress((void**)&p_w2hi,   g_w2hi);
        cudaGetSymbolAddress((void**)&p_w2lo,   g_w2lo);
        cudaFuncSetAttribute(gemm_tc_kernel<128>,
                             cudaFuncAttributeMaxDynamicSharedMemorySize, SMEM1);
        cudaFuncSetAttribute(gemm_tc_kernel<64>,
                             cudaFuncAttributeMaxDynamicSharedMemorySize, SMEM2);
    }

    const int GBLK = (NN + 63) / 64;       // 782

    // ---- one-shot W conversion (also zeroes allocator) ----
    {
        constexpr int NPAIR = (FIN * FHID + FHID * FOUT) / 2;   // 12288
        wconv_kernel<<<(NPAIR + 255) / 256, 256>>>(W1, W2, p_w1hi, p_w1lo, p_w2hi, p_w2lo, p_total);
    }

    // ---- degree + unordered CSR build (no prefix scan) ----
    cudaMemsetAsync(p_deg, 0, (size_t)NN * sizeof(int), 0);
    count_deg_kernel<<<(EE / 4 + 255) / 256, 256>>>(col, p_deg, EE);
    alloc_kernel<<<(NN + 255) / 256, 256>>>(p_deg, p_starts, p_cursor, p_dis, p_total, NN);
    fill_kernel<<<(EE / 4 + 255) / 256, 256>>>(row, col, p_cursor, p_csr, EE);

    // ---- layer 1: tensor GEMM (hs1 = (x@W1)*dis) ----
    gemm_tc_kernel<128><<<GBLK, 256, SMEM1>>>(x, p_w1hi, p_w1lo, p_h, p_dis, NN);

    // ---- layer 1 aggregate -> g_agg = h ----
    {
        long long threads = (long long)NN * 32;
        aggregate_kernel<128, true><<<(int)((threads + 255) / 256), 256>>>(
            p_h, p_csr, p_starts, p_deg, p_dis, b1, p_agg, NN);
    }

    // ---- layer 2: tensor GEMM (hs2 = (h@W2)*dis) ----
    gemm_tc_kernel<64><<<GBLK, 256, SMEM2>>>(p_agg, p_w2hi, p_w2lo, p_h2, p_dis, NN);

    // ---- layer 2 aggregate -> d_out ----
    {
        long long threads = (long long)NN * 16;
        aggregate_kernel<64, false><<<(int)((threads + 255) / 256), 256>>>(
            p_h2, p_csr, p_starts, p_deg, p_dis, b2, out, NN);
    }
}

// round 10
// speedup vs baseline: 1.0833x; 1.0827x over previous
#include <cuda_runtime.h>
#include <cuda_bf16.h>
#include <cuda_fp16.h>
#include <cstdint>

// Problem constants
#define NN   50000
#define EE   800000
#define FIN  128
#define FHID 128
#define FOUT 64

// ---------------------------------------------------------------------------
// Scratch (static __device__ arrays — no allocation allowed)
// ---------------------------------------------------------------------------
__device__ __half g_hs1[(size_t)NN * FHID];  // GEMM1 out: (x@W1)*dis, fp16
__device__ __half g_hh[(size_t)NN * FHID];   // h = relu(dis*sum + b1),  fp16
__device__ __half g_hs2[(size_t)NN * FOUT];  // GEMM2 out: (h@W2)*dis,  fp16
__device__ int    g_deg[NN];                 // in-degree histogram
__device__ float  g_dis[NN];                 // (deg+1)^-1/2
__device__ int    g_starts[NN];              // CSR segment start (unordered ranges)
__device__ int    g_cursor[NN];              // atomic fill cursors
__device__ int    g_csr_row[EE];             // source node per CSR slot
__device__ int    g_total;                   // global range allocator
// Pre-converted weights (hi/lo bf16 split)
__device__ __nv_bfloat16 g_w1hi[FIN * FHID];
__device__ __nv_bfloat16 g_w1lo[FIN * FHID];
__device__ __nv_bfloat16 g_w2hi[FHID * FOUT];
__device__ __nv_bfloat16 g_w2lo[FHID * FOUT];

// ---------------------------------------------------------------------------
// PTX helpers
// ---------------------------------------------------------------------------
__device__ __forceinline__ uint32_t smem_u32(const void* p) {
    return (uint32_t)__cvta_generic_to_shared(p);
}

__device__ __forceinline__ void ldmat_x4(uint32_t& r0, uint32_t& r1, uint32_t& r2, uint32_t& r3,
                                         uint32_t addr) {
    asm volatile("ldmatrix.sync.aligned.m8n8.x4.shared.b16 {%0,%1,%2,%3}, [%4];"
                 : "=r"(r0), "=r"(r1), "=r"(r2), "=r"(r3) : "r"(addr));
}
__device__ __forceinline__ void ldmat_x4_t(uint32_t& r0, uint32_t& r1, uint32_t& r2, uint32_t& r3,
                                           uint32_t addr) {
    asm volatile("ldmatrix.sync.aligned.m8n8.x4.trans.shared.b16 {%0,%1,%2,%3}, [%4];"
                 : "=r"(r0), "=r"(r1), "=r"(r2), "=r"(r3) : "r"(addr));
}

__device__ __forceinline__ void mma_bf16(float* d, const uint32_t* a, uint32_t b0, uint32_t b1) {
    asm volatile(
        "mma.sync.aligned.m16n8k16.row.col.f32.bf16.bf16.f32 "
        "{%0,%1,%2,%3}, {%4,%5,%6,%7}, {%8,%9}, {%0,%1,%2,%3};"
        : "+f"(d[0]), "+f"(d[1]), "+f"(d[2]), "+f"(d[3])
        : "r"(a[0]), "r"(a[1]), "r"(a[2]), "r"(a[3]), "r"(b0), "r"(b1));
}

// pack two fp32 into bf16x2 (hi) and residual bf16x2 (lo)
__device__ __forceinline__ void split2(float v0, float v1, uint32_t& hi, uint32_t& lo) {
    __nv_bfloat16 h0 = __float2bfloat16_rn(v0);
    __nv_bfloat16 h1 = __float2bfloat16_rn(v1);
    __nv_bfloat16 l0 = __float2bfloat16_rn(v0 - __bfloat162float(h0));
    __nv_bfloat16 l1 = __float2bfloat16_rn(v1 - __bfloat162float(h1));
    __nv_bfloat162 ph = {h0, h1}, pl = {l0, l1};
    hi = *(uint32_t*)&ph;
    lo = *(uint32_t*)&pl;
}

// accumulate 8 halves (one uint4) into 8 fp32 accumulators
__device__ __forceinline__ void acc8(float* a, uint4 raw) {
    const __half2* h = (const __half2*)&raw;
#pragma unroll
    for (int j = 0; j < 4; j++) {
        float2 f = __half22float2(h[j]);
        a[2 * j]     += f.x;
        a[2 * j + 1] += f.y;
    }
}

// ---------------------------------------------------------------------------
// One-shot W conversion; also zeroes the range allocator
// ---------------------------------------------------------------------------
__global__ void wconv_kernel(const float* __restrict__ W1, const float* __restrict__ W2,
                             __nv_bfloat16* __restrict__ w1hi, __nv_bfloat16* __restrict__ w1lo,
                             __nv_bfloat16* __restrict__ w2hi, __nv_bfloat16* __restrict__ w2lo,
                             int* __restrict__ total) {
    constexpr int N1 = (FIN * FHID) / 2;
    constexpr int N2 = (FHID * FOUT) / 2;
    int i = blockIdx.x * blockDim.x + threadIdx.x;
    if (i == 0) *total = 0;
    if (i < N1) {
        float2 v = *(const float2*)(W1 + (size_t)i * 2);
        uint32_t hi, lo;
        split2(v.x, v.y, hi, lo);
        *(uint32_t*)(w1hi + (size_t)i * 2) = hi;
        *(uint32_t*)(w1lo + (size_t)i * 2) = lo;
    } else if (i < N1 + N2) {
        int j = i - N1;
        float2 v = *(const float2*)(W2 + (size_t)j * 2);
        uint32_t hi, lo;
        split2(v.x, v.y, hi, lo);
        *(uint32_t*)(w2hi + (size_t)j * 2) = hi;
        *(uint32_t*)(w2lo + (size_t)j * 2) = lo;
    }
}

// ---------------------------------------------------------------------------
// Degree histogram (int4-vectorized, REDs are fire-and-forget)
// ---------------------------------------------------------------------------
__global__ void count_deg_kernel(const int* __restrict__ col, int* __restrict__ deg, int e) {
    int i = blockIdx.x * blockDim.x + threadIdx.x;
    if (i * 4 + 3 < e) {
        int4 c = *(const int4*)(col + i * 4);
        atomicAdd(&deg[c.x], 1);
        atomicAdd(&deg[c.y], 1);
        atomicAdd(&deg[c.z], 1);
        atomicAdd(&deg[c.w], 1);
    } else {
        for (int j = i * 4; j < e; j++) atomicAdd(&deg[col[j]], 1);
    }
}

// ---------------------------------------------------------------------------
// alloc: unordered CSR range allocation via warp-aggregated atomicAdd.
// Also computes dis = rsqrt(deg + 1).
// ---------------------------------------------------------------------------
__global__ void __launch_bounds__(256)
alloc_kernel(const int* __restrict__ deg, int* __restrict__ starts,
             int* __restrict__ cursor, float* __restrict__ dis,
             int* __restrict__ total, int n) {
    int i = blockIdx.x * blockDim.x + threadIdx.x;
    int lane = threadIdx.x & 31;
    int d = (i < n) ? deg[i] : 0;

    int incl = d;
#pragma unroll
    for (int o = 1; o < 32; o <<= 1) {
        int u = __shfl_up_sync(0xffffffffu, incl, o);
        if (lane >= o) incl += u;
    }
    int wtot = __shfl_sync(0xffffffffu, incl, 31);
    int base = 0;
    if (lane == 31 && wtot > 0) base = atomicAdd(total, wtot);
    base = __shfl_sync(0xffffffffu, base, 31);

    if (i < n) {
        int s = base + incl - d;
        starts[i] = s;
        cursor[i] = s;
        dis[i] = rsqrtf((float)d + 1.0f);
    }
}

// ---------------------------------------------------------------------------
// CSR fill — SCALAR (max TLP; int4 version measured slower: occ 76.6->47.6%)
// ---------------------------------------------------------------------------
__global__ void fill_kernel(const int* __restrict__ row, const int* __restrict__ col,
                            int* __restrict__ cursor, int* __restrict__ csr_row, int e) {
    int i = blockIdx.x * blockDim.x + threadIdx.x;
    if (i < e) {
        int slot = atomicAdd(&cursor[col[i]], 1);
        csr_row[slot] = row[i];
    }
}

// ---------------------------------------------------------------------------
// Tensor-core GEMM via split-bf16 (3xBF16 ~ fp32 precision):
//   out[N, F] = (x[N, 128] @ W[128, F]) * dis[row],  out stored fp16.
// TIN = float (layer 1 input) or __half (layer 2 input).
// BM=64, 8 warps (16-row slab x F/2 cols each), 3 CTAs/SM.
// ---------------------------------------------------------------------------
template <int F, typename TIN>
__global__ void __launch_bounds__(256, 3)
gemm_tc_kernel(const TIN* __restrict__ x,
               const __nv_bfloat16* __restrict__ whi_g,
               const __nv_bfloat16* __restrict__ wlo_g,
               __half* __restrict__ out, const float* __restrict__ dis, int nrows) {
    constexpr int BM   = 64;
    constexpr int KT   = 64;
    constexpr int NT   = F / 16;
    constexpr int ASTR = KT + 8;
    constexpr int WSTR = F + 8;

    extern __shared__ __nv_bfloat16 smem[];
    __nv_bfloat16* Ahi = smem;
    __nv_bfloat16* Alo = Ahi + BM * ASTR;
    __nv_bfloat16* Whi = Alo + BM * ASTR;
    __nv_bfloat16* Wlo = Whi + KT * WSTR;

    const int tid  = threadIdx.x;
    const int lane = tid & 31;
    const int w    = tid >> 5;
    const int slab = w >> 1;
    const int ch   = w & 1;
    const int row0 = blockIdx.x * BM;

    float acc[NT][4];
#pragma unroll
    for (int nt = 0; nt < NT; nt++)
#pragma unroll
        for (int j = 0; j < 4; j++) acc[nt][j] = 0.f;

    const int mat  = lane >> 3;
    const int mrow = lane & 7;

    for (int kt = 0; kt < FIN; kt += KT) {
        // ---- A tile: BM x KT (fp32 or fp16) -> hi/lo bf16 ----
        {
            constexpr int NV = (BM * KT) / 4;
#pragma unroll
            for (int p = tid; p < NV; p += 256) {
                int r  = p / (KT / 4);
                int kq = (p % (KT / 4)) * 4;
                float vx, vy, vz, vw;
                int grow = row0 + r;
                if (grow < nrows) {
                    if constexpr (sizeof(TIN) == 4) {
                        float4 v = *(const float4*)((const float*)x + (size_t)grow * FIN + kt + kq);
                        vx = v.x; vy = v.y; vz = v.z; vw = v.w;
                    } else {
                        uint2 u = *(const uint2*)((const __half*)x + (size_t)grow * FIN + kt + kq);
                        const __half2* hh = (const __half2*)&u;
                        float2 f0 = __half22float2(hh[0]);
                        float2 f1 = __half22float2(hh[1]);
                        vx = f0.x; vy = f0.y; vz = f1.x; vw = f1.y;
                    }
                } else {
                    vx = vy = vz = vw = 0.f;
                }
                uint32_t h01, l01, h23, l23;
                split2(vx, vy, h01, l01);
                split2(vz, vw, h23, l23);
                *(uint32_t*)(Ahi + r * ASTR + kq)     = h01;
                *(uint32_t*)(Ahi + r * ASTR + kq + 2) = h23;
                *(uint32_t*)(Alo + r * ASTR + kq)     = l01;
                *(uint32_t*)(Alo + r * ASTR + kq + 2) = l23;
            }
        }
        // ---- W tile: straight bf16 copy ----
        {
            constexpr int NV = (KT * F) / 8;
#pragma unroll
            for (int p = tid; p < NV; p += 256) {
                int k = p / (F / 8);
                int c = (p % (F / 8)) * 8;
                *(uint4*)(Whi + k * WSTR + c) = *(const uint4*)(whi_g + (size_t)(kt + k) * F + c);
                *(uint4*)(Wlo + k * WSTR + c) = *(const uint4*)(wlo_g + (size_t)(kt + k) * F + c);
            }
        }
        __syncthreads();

#pragma unroll
        for (int ks = 0; ks < KT / 16; ks++) {
            uint32_t ah[4], al[4];
            {
                int arow = slab * 16 + (mat & 1) * 8 + mrow;
                int acol = ks * 16 + (mat >> 1) * 8;
                uint32_t a_hi = smem_u32(Ahi + arow * ASTR + acol);
                uint32_t a_lo = smem_u32(Alo + arow * ASTR + acol);
                ldmat_x4(ah[0], ah[1], ah[2], ah[3], a_hi);
                ldmat_x4(al[0], al[1], al[2], al[3], a_lo);
            }
#pragma unroll
            for (int nt2 = 0; nt2 < NT / 2; nt2++) {
                int krow = ks * 16 + (mat & 1) * 8 + mrow;
                int ncol = ch * (F / 2) + nt2 * 16 + (mat >> 1) * 8;
                uint32_t w_hi = smem_u32(Whi + krow * WSTR + ncol);
                uint32_t w_lo = smem_u32(Wlo + krow * WSTR + ncol);
                uint32_t bh[4], bl[4];
                ldmat_x4_t(bh[0], bh[1], bh[2], bh[3], w_hi);
                ldmat_x4_t(bl[0], bl[1], bl[2], bl[3], w_lo);
                mma_bf16(acc[2 * nt2], ah, bh[0], bh[1]);
                mma_bf16(acc[2 * nt2], ah, bl[0], bl[1]);
                mma_bf16(acc[2 * nt2], al, bh[0], bh[1]);
                mma_bf16(acc[2 * nt2 + 1], ah, bh[2], bh[3]);
                mma_bf16(acc[2 * nt2 + 1], ah, bl[2], bl[3]);
                mma_bf16(acc[2 * nt2 + 1], al, bh[2], bh[3]);
            }
        }
        __syncthreads();
    }

    // ---- epilogue: scale by dis[row], write fp16 ----
    {
        int r0 = row0 + slab * 16 + (lane >> 2);
        int r1 = r0 + 8;
        float s0 = (r0 < nrows) ? __ldg(dis + r0) : 0.f;
        float s1 = (r1 < nrows) ? __ldg(dis + r1) : 0.f;
        int cbase = ch * (F / 2) + (lane & 3) * 2;
#pragma unroll
        for (int nt = 0; nt < NT; nt++) {
            int c = cbase + nt * 8;
            if (r0 < nrows)
                *(__half2*)(out + (size_t)r0 * F + c) = __floats2half2_rn(acc[nt][0] * s0, acc[nt][1] * s0);
            if (r1 < nrows)
                *(__half2*)(out + (size_t)r1 * F + c) = __floats2half2_rn(acc[nt][2] * s1, acc[nt][3] * s1);
        }
    }
}

// ---------------------------------------------------------------------------
// CSR segment-sum aggregate over fp16 features; fp32 accumulation.
// Lane = 8 features (one uint4 = 16B). TOUT = __half (layer1 h) or float (out).
// ---------------------------------------------------------------------------
template <int F, bool RELU, typename TOUT>
__global__ void __launch_bounds__(256)
aggregate_kernel(const __half* __restrict__ hs,
                 const int* __restrict__ csr_row, const int* __restrict__ starts,
                 const int* __restrict__ deg,
                 const float* __restrict__ dis, const float* __restrict__ bias,
                 TOUT* __restrict__ out, int n) {
    constexpr int LPN = F / 8;                 // lanes per node
    const int gtid = blockIdx.x * blockDim.x + threadIdx.x;
    const int node = gtid / LPN;
    const int sub  = gtid % LPN;
    if (node >= n) return;

    const int beg = __ldg(starts + node);
    const int end = beg + __ldg(deg + node);

    float a0[8], a1[8], a2[8], a3[8];
#pragma unroll
    for (int j = 0; j < 8; j++) { a0[j] = a1[j] = a2[j] = a3[j] = 0.f; }

    // self loop
    acc8(a0, *(const uint4*)(hs + (size_t)node * F + sub * 8));

    int e = beg;
    for (; e + 3 < end; e += 4) {
        int r0 = __ldg(csr_row + e);
        int r1 = __ldg(csr_row + e + 1);
        int r2 = __ldg(csr_row + e + 2);
        int r3 = __ldg(csr_row + e + 3);
        uint4 v0 = *(const uint4*)(hs + (size_t)r0 * F + sub * 8);
        uint4 v1 = *(const uint4*)(hs + (size_t)r1 * F + sub * 8);
        uint4 v2 = *(const uint4*)(hs + (size_t)r2 * F + sub * 8);
        uint4 v3 = *(const uint4*)(hs + (size_t)r3 * F + sub * 8);
        acc8(a0, v0); acc8(a1, v1); acc8(a2, v2); acc8(a3, v3);
    }
    for (; e < end; e++) {
        int r0 = __ldg(csr_row + e);
        acc8(a0, *(const uint4*)(hs + (size_t)r0 * F + sub * 8));
    }

    const float d = __ldg(dis + node);
    float4 bva = *(const float4*)(bias + sub * 8);
    float4 bvb = *(const float4*)(bias + sub * 8 + 4);
    float o[8];
#pragma unroll
    for (int j = 0; j < 8; j++) {
        float bj = (j < 4) ? ((const float*)&bva)[j] : ((const float*)&bvb)[j - 4];
        o[j] = (a0[j] + a1[j] + a2[j] + a3[j]) * d + bj;
        if (RELU) o[j] = fmaxf(o[j], 0.f);
    }

    if constexpr (sizeof(TOUT) == 2) {
        __half2 p[4];
#pragma unroll
        for (int j = 0; j < 4; j++) p[j] = __floats2half2_rn(o[2 * j], o[2 * j + 1]);
        *(uint4*)((__half*)out + (size_t)node * F + sub * 8) = *(uint4*)p;
    } else {
        float* op = (float*)out + (size_t)node * F + sub * 8;
        *(float4*)(op)     = make_float4(o[0], o[1], o[2], o[3]);
        *(float4*)(op + 4) = make_float4(o[4], o[5], o[6], o[7]);
    }
}

// ---------------------------------------------------------------------------
// Launch (single stream, sequential)
// ---------------------------------------------------------------------------
extern "C" void kernel_launch(void* const* d_in, const int* in_sizes, int n_in,
                              void* d_out, int out_size) {
    const float* x  = (const float*)d_in[0];
    const int*   ei = (const int*)d_in[1];
    const float* W1 = (const float*)d_in[2];
    const float* b1 = (const float*)d_in[3];
    const float* W2 = (const float*)d_in[4];
    const float* b2 = (const float*)d_in[5];
    float* out = (float*)d_out;

    const int* row = ei;
    const int* col = ei + EE;

    constexpr int SMEM1 = (64 * 72 * 2 + 64 * 136 * 2) * 2;  // 53,248 B (F=128)
    constexpr int SMEM2 = (64 * 72 * 2 + 64 * 72 * 2) * 2;   // 36,864 B (F=64)

    static __half *p_hs1 = nullptr, *p_hh = nullptr, *p_hs2 = nullptr;
    static float *p_dis = nullptr;
    static int *p_deg = nullptr, *p_starts = nullptr, *p_cursor = nullptr,
               *p_csr = nullptr, *p_total = nullptr;
    static __nv_bfloat16 *p_w1hi = nullptr, *p_w1lo = nullptr, *p_w2hi = nullptr, *p_w2lo = nullptr;
    if (!p_hs1) {
        cudaGetSymbolAddress((void**)&p_hs1,    g_hs1);
        cudaGetSymbolAddress((void**)&p_hh,     g_hh);
        cudaGetSymbolAddress((void**)&p_hs2,    g_hs2);
        cudaGetSymbolAddress((void**)&p_dis,    g_dis);
        cudaGetSymbolAddress((void**)&p_deg,    g_deg);
        cudaGetSymbolAddress((void**)&p_starts, g_starts);
        cudaGetSymbolAddress((void**)&p_cursor, g_cursor);
        cudaGetSymbolAddress((void**)&p_csr,    g_csr_row);
        cudaGetSymbolAddress((void**)&p_total,  g_total);
        cudaGetSymbolAddress((void**)&p_w1hi,   g_w1hi);
        cudaGetSymbolAddress((void**)&p_w1lo,   g_w1lo);
        cudaGetSymbolAddress((void**)&p_w2hi,   g_w2hi);
        cudaGetSymbolAddress((void**)&p_w2lo,   g_w2lo);
        cudaFuncSetAttribute((const void*)gemm_tc_kernel<128, float>,
                             cudaFuncAttributeMaxDynamicSharedMemorySize, SMEM1);
        cudaFuncSetAttribute((const void*)gemm_tc_kernel<64, __half>,
                             cudaFuncAttributeMaxDynamicSharedMemorySize, SMEM2);
    }

    const int GBLK = (NN + 63) / 64;       // 782

    // ---- one-shot W conversion (also zeroes allocator) ----
    {
        constexpr int NPAIR = (FIN * FHID + FHID * FOUT) / 2;
        wconv_kernel<<<(NPAIR + 255) / 256, 256>>>(W1, W2, p_w1hi, p_w1lo, p_w2hi, p_w2lo, p_total);
    }

    // ---- degree + unordered CSR build ----
    cudaMemsetAsync(p_deg, 0, (size_t)NN * sizeof(int), 0);
    count_deg_kernel<<<(EE / 4 + 255) / 256, 256>>>(col, p_deg, EE);
    alloc_kernel<<<(NN + 255) / 256, 256>>>(p_deg, p_starts, p_cursor, p_dis, p_total, NN);
    fill_kernel<<<(EE + 255) / 256, 256>>>(row, col, p_cursor, p_csr, EE);

    // ---- layer 1: tensor GEMM (hs1 = (x@W1)*dis, fp16 out) ----
    gemm_tc_kernel<128, float><<<GBLK, 256, SMEM1>>>(x, p_w1hi, p_w1lo, p_hs1, p_dis, NN);

    // ---- layer 1 aggregate -> h (fp16) ----
    {
        long long threads = (long long)NN * (FHID / 8);   // 800k
        aggregate_kernel<128, true, __half><<<(int)((threads + 255) / 256), 256>>>(
            p_hs1, p_csr, p_starts, p_deg, p_dis, b1, p_hh, NN);
    }

    // ---- layer 2: tensor GEMM (hs2 = (h@W2)*dis, fp16 out) ----
    gemm_tc_kernel<64, __half><<<GBLK, 256, SMEM2>>>(p_hh, p_w2hi, p_w2lo, p_hs2, p_dis, NN);

    // ---- layer 2 aggregate -> d_out (fp32) ----
    {
        long long threads = (long long)NN * (FOUT / 8);   // 400k
        aggregate_kernel<64, false, float><<<(int)((threads + 255) / 256), 256>>>(
            p_hs2, p_csr, p_starts, p_deg, p_dis, b2, out, NN);
    }
}

// round 11
// speedup vs baseline: 1.3076x; 1.2070x over previous
#include <cuda_runtime.h>
#include <cuda_bf16.h>
#include <cuda_fp16.h>
#include <cstdint>

// Problem constants
#define NN   50000
#define EE   800000
#define FIN  128
#define FHID 128
#define FOUT 64
#define SLOTS 64   // max in-degree slots per node (Poisson(16): P(deg>=64) ~ 1e-20)

// ---------------------------------------------------------------------------
// Scratch (static __device__ arrays — no allocation allowed)
// ---------------------------------------------------------------------------
__device__ __half g_hs1[(size_t)NN * FHID];  // GEMM1 out: (x@W1)*dis, fp16
__device__ __half g_hh[(size_t)NN * FHID];   // h = relu(dis*sum + b1),  fp16
__device__ __half g_hs2[(size_t)NN * FOUT];  // GEMM2 out: (h@W2)*dis,  fp16
__device__ int    g_cnt[NN];                 // per-node edge count (atomic)
__device__ float  g_dis[NN];                 // (deg+1)^-1/2
__device__ int    g_slots[(size_t)NN * SLOTS]; // direct-mapped CSR: sources per node
// Pre-converted fp16 weights
__device__ __half g_w1h[FIN * FHID];
__device__ __half g_w2h[FHID * FOUT];

// ---------------------------------------------------------------------------
// PTX helpers
// ---------------------------------------------------------------------------
__device__ __forceinline__ uint32_t smem_u32(const void* p) {
    return (uint32_t)__cvta_generic_to_shared(p);
}

__device__ __forceinline__ void ldmat_x4(uint32_t& r0, uint32_t& r1, uint32_t& r2, uint32_t& r3,
                                         uint32_t addr) {
    asm volatile("ldmatrix.sync.aligned.m8n8.x4.shared.b16 {%0,%1,%2,%3}, [%4];"
                 : "=r"(r0), "=r"(r1), "=r"(r2), "=r"(r3) : "r"(addr));
}
__device__ __forceinline__ void ldmat_x4_t(uint32_t& r0, uint32_t& r1, uint32_t& r2, uint32_t& r3,
                                           uint32_t addr) {
    asm volatile("ldmatrix.sync.aligned.m8n8.x4.trans.shared.b16 {%0,%1,%2,%3}, [%4];"
                 : "=r"(r0), "=r"(r1), "=r"(r2), "=r"(r3) : "r"(addr));
}

__device__ __forceinline__ void mma_f16(float* d, const uint32_t* a, uint32_t b0, uint32_t b1) {
    asm volatile(
        "mma.sync.aligned.m16n8k16.row.col.f32.f16.f16.f32 "
        "{%0,%1,%2,%3}, {%4,%5,%6,%7}, {%8,%9}, {%0,%1,%2,%3};"
        : "+f"(d[0]), "+f"(d[1]), "+f"(d[2]), "+f"(d[3])
        : "r"(a[0]), "r"(a[1]), "r"(a[2]), "r"(a[3]), "r"(b0), "r"(b1));
}

// accumulate 8 halves (one uint4) into 8 fp32 accumulators
__device__ __forceinline__ void acc8(float* a, uint4 raw) {
    const __half2* h = (const __half2*)&raw;
#pragma unroll
    for (int j = 0; j < 4; j++) {
        float2 f = __half22float2(h[j]);
        a[2 * j]     += f.x;
        a[2 * j + 1] += f.y;
    }
}

// ---------------------------------------------------------------------------
// One-shot W conversion fp32 -> fp16
// ---------------------------------------------------------------------------
__global__ void wconv_kernel(const float* __restrict__ W1, const float* __restrict__ W2,
                             __half* __restrict__ w1h, __half* __restrict__ w2h) {
    constexpr int N1 = (FIN * FHID) / 2;
    constexpr int N2 = (FHID * FOUT) / 2;
    int i = blockIdx.x * blockDim.x + threadIdx.x;
    if (i < N1) {
        float2 v = *(const float2*)(W1 + (size_t)i * 2);
        *(__half2*)(w1h + (size_t)i * 2) = __floats2half2_rn(v.x, v.y);
    } else if (i < N1 + N2) {
        int j = i - N1;
        float2 v = *(const float2*)(W2 + (size_t)j * 2);
        *(__half2*)(w2h + (size_t)j * 2) = __floats2half2_rn(v.x, v.y);
    }
}

// ---------------------------------------------------------------------------
// Single-pass CSR build: slot = cnt[col]++; slots[col*SLOTS + slot] = row
// (replaces count_deg + alloc + fill: half the atomic traffic, 2 fewer kernels)
// ---------------------------------------------------------------------------
__global__ void fill_direct_kernel(const int* __restrict__ row, const int* __restrict__ col,
                                   int* __restrict__ cnt, int* __restrict__ slots, int e) {
    int i = blockIdx.x * blockDim.x + threadIdx.x;
    if (i < e) {
        int c = col[i];
        int s = atomicAdd(&cnt[c], 1);
        slots[(size_t)c * SLOTS + s] = row[i];
    }
}

// dis = rsqrt(deg + 1)
__global__ void dis_kernel(const int* __restrict__ cnt, float* __restrict__ dis, int n) {
    int i = blockIdx.x * blockDim.x + threadIdx.x;
    if (i < n) dis[i] = rsqrtf((float)cnt[i] + 1.0f);
}

// ---------------------------------------------------------------------------
// Tensor-core GEMM, plain fp16 inputs (1 MMA per tile step):
//   out[N, F] = (x[N, 128] @ W[128, F]) * dis[row],  out stored fp16.
// TIN = float (layer 1) or __half (layer 2 — straight smem copy).
// BM=64, 8 warps (warp = 16-row slab x F/2 cols), 3 CTAs/SM.
// ---------------------------------------------------------------------------
template <int F, typename TIN>
__global__ void __launch_bounds__(256, 3)
gemm_tc_kernel(const TIN* __restrict__ x,
               const __half* __restrict__ wg,
               __half* __restrict__ out, const float* __restrict__ dis, int nrows) {
    constexpr int BM   = 64;
    constexpr int KT   = 64;
    constexpr int NT   = F / 16;
    constexpr int ASTR = KT + 8;     // 72 halves (144 B row stride)
    constexpr int WSTR = F + 8;

    extern __shared__ __half smem[];
    __half* Ah = smem;               // [BM][ASTR]
    __half* Wh = Ah + BM * ASTR;     // [KT][WSTR]

    const int tid  = threadIdx.x;
    const int lane = tid & 31;
    const int w    = tid >> 5;
    const int slab = w >> 1;
    const int ch   = w & 1;
    const int row0 = blockIdx.x * BM;

    float acc[NT][4];
#pragma unroll
    for (int nt = 0; nt < NT; nt++)
#pragma unroll
        for (int j = 0; j < 4; j++) acc[nt][j] = 0.f;

    const int mat  = lane >> 3;
    const int mrow = lane & 7;

    for (int kt = 0; kt < FIN; kt += KT) {
        // ---- A tile ----
        if constexpr (sizeof(TIN) == 4) {
            constexpr int NV = (BM * KT) / 4;    // float4 per thread
#pragma unroll
            for (int p = tid; p < NV; p += 256) {
                int r  = p / (KT / 4);
                int kq = (p % (KT / 4)) * 4;
                float4 v;
                int grow = row0 + r;
                if (grow < nrows)
                    v = *(const float4*)((const float*)x + (size_t)grow * FIN + kt + kq);
                else
                    v = make_float4(0.f, 0.f, 0.f, 0.f);
                *(__half2*)(Ah + r * ASTR + kq)     = __floats2half2_rn(v.x, v.y);
                *(__half2*)(Ah + r * ASTR + kq + 2) = __floats2half2_rn(v.z, v.w);
            }
        } else {
            constexpr int NV = (BM * KT) / 8;    // uint4 (8 halves) per thread
#pragma unroll
            for (int p = tid; p < NV; p += 256) {
                int r  = p / (KT / 8);
                int kq = (p % (KT / 8)) * 8;
                uint4 v;
                int grow = row0 + r;
                if (grow < nrows)
                    v = *(const uint4*)((const __half*)x + (size_t)grow * FIN + kt + kq);
                else
                    v = make_uint4(0, 0, 0, 0);
                *(uint4*)(Ah + r * ASTR + kq) = v;
            }
        }
        // ---- W tile: straight fp16 copy ----
        {
            constexpr int NV = (KT * F) / 8;
#pragma unroll
            for (int p = tid; p < NV; p += 256) {
                int k = p / (F / 8);
                int c = (p % (F / 8)) * 8;
                *(uint4*)(Wh + k * WSTR + c) = *(const uint4*)(wg + (size_t)(kt + k) * F + c);
            }
        }
        __syncthreads();

#pragma unroll
        for (int ks = 0; ks < KT / 16; ks++) {
            uint32_t ah[4];
            {
                int arow = slab * 16 + (mat & 1) * 8 + mrow;
                int acol = ks * 16 + (mat >> 1) * 8;
                ldmat_x4(ah[0], ah[1], ah[2], ah[3], smem_u32(Ah + arow * ASTR + acol));
            }
#pragma unroll
            for (int nt2 = 0; nt2 < NT / 2; nt2++) {
                int krow = ks * 16 + (mat & 1) * 8 + mrow;
                int ncol = ch * (F / 2) + nt2 * 16 + (mat >> 1) * 8;
                uint32_t bh[4];
                ldmat_x4_t(bh[0], bh[1], bh[2], bh[3], smem_u32(Wh + krow * WSTR + ncol));
                mma_f16(acc[2 * nt2],     ah, bh[0], bh[1]);
                mma_f16(acc[2 * nt2 + 1], ah, bh[2], bh[3]);
            }
        }
        __syncthreads();
    }

    // ---- epilogue: scale by dis[row], write fp16 ----
    {
        int r0 = row0 + slab * 16 + (lane >> 2);
        int r1 = r0 + 8;
        float s0 = (r0 < nrows) ? __ldg(dis + r0) : 0.f;
        float s1 = (r1 < nrows) ? __ldg(dis + r1) : 0.f;
        int cbase = ch * (F / 2) + (lane & 3) * 2;
#pragma unroll
        for (int nt = 0; nt < NT; nt++) {
            int c = cbase + nt * 8;
            if (r0 < nrows)
                *(__half2*)(out + (size_t)r0 * F + c) = __floats2half2_rn(acc[nt][0] * s0, acc[nt][1] * s0);
            if (r1 < nrows)
                *(__half2*)(out + (size_t)r1 * F + c) = __floats2half2_rn(acc[nt][2] * s1, acc[nt][3] * s1);
        }
    }
}

// ---------------------------------------------------------------------------
// Segment-sum aggregate over fp16 features; fp32 accumulation.
// Segment for node i = slots[i*SLOTS .. i*SLOTS + cnt[i]).
// Lane = 8 features (one uint4). TOUT = __half (layer1 h) or float (out).
// ---------------------------------------------------------------------------
template <int F, bool RELU, typename TOUT>
__global__ void __launch_bounds__(256)
aggregate_kernel(const __half* __restrict__ hs,
                 const int* __restrict__ slots, const int* __restrict__ cnt,
                 const float* __restrict__ dis, const float* __restrict__ bias,
                 TOUT* __restrict__ out, int n) {
    constexpr int LPN = F / 8;
    const int gtid = blockIdx.x * blockDim.x + threadIdx.x;
    const int node = gtid / LPN;
    const int sub  = gtid % LPN;
    if (node >= n) return;

    const int beg = node * SLOTS;
    const int end = beg + __ldg(cnt + node);

    float a0[8], a1[8], a2[8], a3[8];
#pragma unroll
    for (int j = 0; j < 8; j++) { a0[j] = a1[j] = a2[j] = a3[j] = 0.f; }

    // self loop
    acc8(a0, *(const uint4*)(hs + (size_t)node * F + sub * 8));

    int e = beg;
    for (; e + 3 < end; e += 4) {
        int r0 = __ldg(slots + e);
        int r1 = __ldg(slots + e + 1);
        int r2 = __ldg(slots + e + 2);
        int r3 = __ldg(slots + e + 3);
        uint4 v0 = *(const uint4*)(hs + (size_t)r0 * F + sub * 8);
        uint4 v1 = *(const uint4*)(hs + (size_t)r1 * F + sub * 8);
        uint4 v2 = *(const uint4*)(hs + (size_t)r2 * F + sub * 8);
        uint4 v3 = *(const uint4*)(hs + (size_t)r3 * F + sub * 8);
        acc8(a0, v0); acc8(a1, v1); acc8(a2, v2); acc8(a3, v3);
    }
    for (; e < end; e++) {
        int r0 = __ldg(slots + e);
        acc8(a0, *(const uint4*)(hs + (size_t)r0 * F + sub * 8));
    }

    const float d = __ldg(dis + node);
    float4 bva = *(const float4*)(bias + sub * 8);
    float4 bvb = *(const float4*)(bias + sub * 8 + 4);
    float o[8];
#pragma unroll
    for (int j = 0; j < 8; j++) {
        float bj = (j < 4) ? ((const float*)&bva)[j] : ((const float*)&bvb)[j - 4];
        o[j] = (a0[j] + a1[j] + a2[j] + a3[j]) * d + bj;
        if (RELU) o[j] = fmaxf(o[j], 0.f);
    }

    if constexpr (sizeof(TOUT) == 2) {
        __half2 p[4];
#pragma unroll
        for (int j = 0; j < 4; j++) p[j] = __floats2half2_rn(o[2 * j], o[2 * j + 1]);
        *(uint4*)((__half*)out + (size_t)node * F + sub * 8) = *(uint4*)p;
    } else {
        float* op = (float*)out + (size_t)node * F + sub * 8;
        *(float4*)(op)     = make_float4(o[0], o[1], o[2], o[3]);
        *(float4*)(op + 4) = make_float4(o[4], o[5], o[6], o[7]);
    }
}

// ---------------------------------------------------------------------------
// Launch (single stream, sequential)
// ---------------------------------------------------------------------------
extern "C" void kernel_launch(void* const* d_in, const int* in_sizes, int n_in,
                              void* d_out, int out_size) {
    const float* x  = (const float*)d_in[0];
    const int*   ei = (const int*)d_in[1];
    const float* W1 = (const float*)d_in[2];
    const float* b1 = (const float*)d_in[3];
    const float* W2 = (const float*)d_in[4];
    const float* b2 = (const float*)d_in[5];
    float* out = (float*)d_out;

    const int* row = ei;
    const int* col = ei + EE;

    constexpr int SMEM1 = (64 * 72 + 64 * 136) * 2;  // 26,624 B (F=128)
    constexpr int SMEM2 = (64 * 72 + 64 * 72) * 2;   // 18,432 B (F=64)

    static __half *p_hs1 = nullptr, *p_hh = nullptr, *p_hs2 = nullptr,
                  *p_w1h = nullptr, *p_w2h = nullptr;
    static float *p_dis = nullptr;
    static int *p_cnt = nullptr, *p_slots = nullptr;
    if (!p_hs1) {
        cudaGetSymbolAddress((void**)&p_hs1,   g_hs1);
        cudaGetSymbolAddress((void**)&p_hh,    g_hh);
        cudaGetSymbolAddress((void**)&p_hs2,   g_hs2);
        cudaGetSymbolAddress((void**)&p_dis,   g_dis);
        cudaGetSymbolAddress((void**)&p_cnt,   g_cnt);
        cudaGetSymbolAddress((void**)&p_slots, g_slots);
        cudaGetSymbolAddress((void**)&p_w1h,   g_w1h);
        cudaGetSymbolAddress((void**)&p_w2h,   g_w2h);
        cudaFuncSetAttribute((const void*)gemm_tc_kernel<128, float>,
                             cudaFuncAttributeMaxDynamicSharedMemorySize, SMEM1);
        cudaFuncSetAttribute((const void*)gemm_tc_kernel<64, __half>,
                             cudaFuncAttributeMaxDynamicSharedMemorySize, SMEM2);
    }

    const int GBLK = (NN + 63) / 64;       // 782

    // ---- one-shot W conversion ----
    {
        constexpr int NPAIR = (FIN * FHID + FHID * FOUT) / 2;
        wconv_kernel<<<(NPAIR + 255) / 256, 256>>>(W1, W2, p_w1h, p_w2h);
    }

    // ---- single-pass CSR build + dis ----
    cudaMemsetAsync(p_cnt, 0, (size_t)NN * sizeof(int), 0);
    fill_direct_kernel<<<(EE + 255) / 256, 256>>>(row, col, p_cnt, p_slots, EE);
    dis_kernel<<<(NN + 255) / 256, 256>>>(p_cnt, p_dis, NN);

    // ---- layer 1: fp16 tensor GEMM (hs1 = (x@W1)*dis) ----
    gemm_tc_kernel<128, float><<<GBLK, 256, SMEM1>>>(x, p_w1h, p_hs1, p_dis, NN);

    // ---- layer 1 aggregate -> h (fp16) ----
    {
        long long threads = (long long)NN * (FHID / 8);
        aggregate_kernel<128, true, __half><<<(int)((threads + 255) / 256), 256>>>(
            p_hs1, p_slots, p_cnt, p_dis, b1, p_hh, NN);
    }

    // ---- layer 2: fp16 tensor GEMM (hs2 = (h@W2)*dis) ----
    gemm_tc_kernel<64, __half><<<GBLK, 256, SMEM2>>>(p_hh, p_w2h, p_hs2, p_dis, NN);

    // ---- layer 2 aggregate -> d_out (fp32) ----
    {
        long long threads = (long long)NN * (FOUT / 8);
        aggregate_kernel<64, false, float><<<(int)((threads + 255) / 256), 256>>>(
            p_hs2, p_slots, p_cnt, p_dis, b2, out, NN);
    }
}

// round 12
// speedup vs baseline: 1.3387x; 1.0238x over previous
#include <cuda_runtime.h>
#include <cuda_bf16.h>
#include <cuda_fp16.h>
#include <cstdint>

// Problem constants
#define NN   50000
#define EE   800000
#define FIN  128
#define FHID 128
#define FOUT 64
#define SLOTS 64   // max in-degree slots per node (Poisson(16): P(deg>=64) ~ 1e-20)

// ---------------------------------------------------------------------------
// Scratch (static __device__ arrays — no allocation allowed)
// ---------------------------------------------------------------------------
__device__ __half g_hs1[(size_t)NN * FHID];  // GEMM1 out: (x@W1)*dis, fp16
__device__ __half g_hh[(size_t)NN * FHID];   // h = relu(dis*sum + b1),  fp16
__device__ __half g_hs2[(size_t)NN * FOUT];  // GEMM2 out: (h@W2)*dis,  fp16
__device__ int    g_cnt[NN];                 // per-node edge count (atomic)
__device__ int    g_slots[(size_t)NN * SLOTS]; // direct-mapped CSR: sources per node
// Pre-converted fp16 weights
__device__ __half g_w1h[FIN * FHID];
__device__ __half g_w2h[FHID * FOUT];

// ---------------------------------------------------------------------------
// PTX helpers
// ---------------------------------------------------------------------------
__device__ __forceinline__ uint32_t smem_u32(const void* p) {
    return (uint32_t)__cvta_generic_to_shared(p);
}

__device__ __forceinline__ void ldmat_x4(uint32_t& r0, uint32_t& r1, uint32_t& r2, uint32_t& r3,
                                         uint32_t addr) {
    asm volatile("ldmatrix.sync.aligned.m8n8.x4.shared.b16 {%0,%1,%2,%3}, [%4];"
                 : "=r"(r0), "=r"(r1), "=r"(r2), "=r"(r3) : "r"(addr));
}
__device__ __forceinline__ void ldmat_x4_t(uint32_t& r0, uint32_t& r1, uint32_t& r2, uint32_t& r3,
                                           uint32_t addr) {
    asm volatile("ldmatrix.sync.aligned.m8n8.x4.trans.shared.b16 {%0,%1,%2,%3}, [%4];"
                 : "=r"(r0), "=r"(r1), "=r"(r2), "=r"(r3) : "r"(addr));
}

__device__ __forceinline__ void mma_f16(float* d, const uint32_t* a, uint32_t b0, uint32_t b1) {
    asm volatile(
        "mma.sync.aligned.m16n8k16.row.col.f32.f16.f16.f32 "
        "{%0,%1,%2,%3}, {%4,%5,%6,%7}, {%8,%9}, {%0,%1,%2,%3};"
        : "+f"(d[0]), "+f"(d[1]), "+f"(d[2]), "+f"(d[3])
        : "r"(a[0]), "r"(a[1]), "r"(a[2]), "r"(a[3]), "r"(b0), "r"(b1));
}

// accumulate 8 halves (one uint4) into 8 fp32 accumulators
__device__ __forceinline__ void acc8(float* a, uint4 raw) {
    const __half2* h = (const __half2*)&raw;
#pragma unroll
    for (int j = 0; j < 4; j++) {
        float2 f = __half22float2(h[j]);
        a[2 * j]     += f.x;
        a[2 * j + 1] += f.y;
    }
}

// ---------------------------------------------------------------------------
// One-shot W conversion fp32 -> fp16
// ---------------------------------------------------------------------------
__global__ void wconv_kernel(const float* __restrict__ W1, const float* __restrict__ W2,
                             __half* __restrict__ w1h, __half* __restrict__ w2h) {
    constexpr int N1 = (FIN * FHID) / 2;
    constexpr int N2 = (FHID * FOUT) / 2;
    int i = blockIdx.x * blockDim.x + threadIdx.x;
    if (i < N1) {
        float2 v = *(const float2*)(W1 + (size_t)i * 2);
        *(__half2*)(w1h + (size_t)i * 2) = __floats2half2_rn(v.x, v.y);
    } else if (i < N1 + N2) {
        int j = i - N1;
        float2 v = *(const float2*)(W2 + (size_t)j * 2);
        *(__half2*)(w2h + (size_t)j * 2) = __floats2half2_rn(v.x, v.y);
    }
}

// ---------------------------------------------------------------------------
// Single-pass CSR build: slot = cnt[col]++; slots[col*SLOTS + slot] = row
// ---------------------------------------------------------------------------
__global__ void fill_direct_kernel(const int* __restrict__ row, const int* __restrict__ col,
                                   int* __restrict__ cnt, int* __restrict__ slots, int e) {
    int i = blockIdx.x * blockDim.x + threadIdx.x;
    if (i < e) {
        int c = col[i];
        int s = atomicAdd(&cnt[c], 1);
        slots[(size_t)c * SLOTS + s] = row[i];
    }
}

// ---------------------------------------------------------------------------
// Tensor-core GEMM, fp16 inputs, FULL K (=128) resident in smem:
//   out[N, F] = (x[N, 128] @ W[128, F]) * rsqrt(cnt[row]+1),  out fp16.
// ONE __syncthreads per block, then 8 back-to-back k-steps of MMAs.
// BM=64, 8 warps (warp = 16-row slab x F/2 cols).
// smem: F=128 -> 52.2KB (4 CTAs/SM), F=64 -> 35.8KB (6 CTAs/SM).
// ---------------------------------------------------------------------------
template <int F, typename TIN>
__global__ void __launch_bounds__(256)
gemm_tc_kernel(const TIN* __restrict__ x,
               const __half* __restrict__ wg,
               __half* __restrict__ out, const int* __restrict__ cnt, int nrows) {
    constexpr int BM   = 64;
    constexpr int KT   = 128;        // full reduction depth
    constexpr int NT   = F / 16;
    constexpr int ASTR = KT + 8;     // 136 halves
    constexpr int WSTR = F + 8;

    extern __shared__ __half smem[];
    __half* Ah = smem;               // [BM][ASTR]
    __half* Wh = Ah + BM * ASTR;     // [KT][WSTR]

    const int tid  = threadIdx.x;
    const int lane = tid & 31;
    const int w    = tid >> 5;
    const int slab = w >> 1;
    const int ch   = w & 1;
    const int row0 = blockIdx.x * BM;

    float acc[NT][4];
#pragma unroll
    for (int nt = 0; nt < NT; nt++)
#pragma unroll
        for (int j = 0; j < 4; j++) acc[nt][j] = 0.f;

    const int mat  = lane >> 3;
    const int mrow = lane & 7;

    // ---- A tile (whole 64 x 128) ----
    if constexpr (sizeof(TIN) == 4) {
        constexpr int NV = (BM * KT) / 4;    // 2048 float4
#pragma unroll
        for (int p = tid; p < NV; p += 256) {
            int r  = p / (KT / 4);
            int kq = (p % (KT / 4)) * 4;
            float4 v;
            int grow = row0 + r;
            if (grow < nrows)
                v = *(const float4*)((const float*)x + (size_t)grow * FIN + kq);
            else
                v = make_float4(0.f, 0.f, 0.f, 0.f);
            *(__half2*)(Ah + r * ASTR + kq)     = __floats2half2_rn(v.x, v.y);
            *(__half2*)(Ah + r * ASTR + kq + 2) = __floats2half2_rn(v.z, v.w);
        }
    } else {
        constexpr int NV = (BM * KT) / 8;    // 1024 uint4
#pragma unroll
        for (int p = tid; p < NV; p += 256) {
            int r  = p / (KT / 8);
            int kq = (p % (KT / 8)) * 8;
            uint4 v;
            int grow = row0 + r;
            if (grow < nrows)
                v = *(const uint4*)((const __half*)x + (size_t)grow * FIN + kq);
            else
                v = make_uint4(0, 0, 0, 0);
            *(uint4*)(Ah + r * ASTR + kq) = v;
        }
    }
    // ---- W tile (whole 128 x F), straight fp16 copy ----
    {
        constexpr int NV = (KT * F) / 8;
#pragma unroll
        for (int p = tid; p < NV; p += 256) {
            int k = p / (F / 8);
            int c = (p % (F / 8)) * 8;
            *(uint4*)(Wh + k * WSTR + c) = *(const uint4*)(wg + (size_t)k * F + c);
        }
    }
    __syncthreads();   // the ONLY barrier

#pragma unroll
    for (int ks = 0; ks < KT / 16; ks++) {
        uint32_t ah[4];
        {
            int arow = slab * 16 + (mat & 1) * 8 + mrow;
            int acol = ks * 16 + (mat >> 1) * 8;
            ldmat_x4(ah[0], ah[1], ah[2], ah[3], smem_u32(Ah + arow * ASTR + acol));
        }
#pragma unroll
        for (int nt2 = 0; nt2 < NT / 2; nt2++) {
            int krow = ks * 16 + (mat & 1) * 8 + mrow;
            int ncol = ch * (F / 2) + nt2 * 16 + (mat >> 1) * 8;
            uint32_t bh[4];
            ldmat_x4_t(bh[0], bh[1], bh[2], bh[3], smem_u32(Wh + krow * WSTR + ncol));
            mma_f16(acc[2 * nt2],     ah, bh[0], bh[1]);
            mma_f16(acc[2 * nt2 + 1], ah, bh[2], bh[3]);
        }
    }

    // ---- epilogue: scale by rsqrt(cnt+1), write fp16 ----
    {
        int r0 = row0 + slab * 16 + (lane >> 2);
        int r1 = r0 + 8;
        float s0 = (r0 < nrows) ? rsqrtf((float)__ldg(cnt + r0) + 1.0f) : 0.f;
        float s1 = (r1 < nrows) ? rsqrtf((float)__ldg(cnt + r1) + 1.0f) : 0.f;
        int cbase = ch * (F / 2) + (lane & 3) * 2;
#pragma unroll
        for (int nt = 0; nt < NT; nt++) {
            int c = cbase + nt * 8;
            if (r0 < nrows)
                *(__half2*)(out + (size_t)r0 * F + c) = __floats2half2_rn(acc[nt][0] * s0, acc[nt][1] * s0);
            if (r1 < nrows)
                *(__half2*)(out + (size_t)r1 * F + c) = __floats2half2_rn(acc[nt][2] * s1, acc[nt][3] * s1);
        }
    }
}

// ---------------------------------------------------------------------------
// Segment-sum aggregate over fp16 features; fp32 accumulation.
// Segment for node i = slots[i*SLOTS .. i*SLOTS + cnt[i]); dis computed inline.
// ---------------------------------------------------------------------------
template <int F, bool RELU, typename TOUT>
__global__ void __launch_bounds__(256)
aggregate_kernel(const __half* __restrict__ hs,
                 const int* __restrict__ slots, const int* __restrict__ cnt,
                 const float* __restrict__ bias,
                 TOUT* __restrict__ out, int n) {
    constexpr int LPN = F / 8;
    const int gtid = blockIdx.x * blockDim.x + threadIdx.x;
    const int node = gtid / LPN;
    const int sub  = gtid % LPN;
    if (node >= n) return;

    const int deg = __ldg(cnt + node);
    const int beg = node * SLOTS;
    const int end = beg + deg;

    float a0[8], a1[8], a2[8], a3[8];
#pragma unroll
    for (int j = 0; j < 8; j++) { a0[j] = a1[j] = a2[j] = a3[j] = 0.f; }

    // self loop
    acc8(a0, *(const uint4*)(hs + (size_t)node * F + sub * 8));

    int e = beg;
    for (; e + 3 < end; e += 4) {
        int r0 = __ldg(slots + e);
        int r1 = __ldg(slots + e + 1);
        int r2 = __ldg(slots + e + 2);
        int r3 = __ldg(slots + e + 3);
        uint4 v0 = *(const uint4*)(hs + (size_t)r0 * F + sub * 8);
        uint4 v1 = *(const uint4*)(hs + (size_t)r1 * F + sub * 8);
        uint4 v2 = *(const uint4*)(hs + (size_t)r2 * F + sub * 8);
        uint4 v3 = *(const uint4*)(hs + (size_t)r3 * F + sub * 8);
        acc8(a0, v0); acc8(a1, v1); acc8(a2, v2); acc8(a3, v3);
    }
    for (; e < end; e++) {
        int r0 = __ldg(slots + e);
        acc8(a0, *(const uint4*)(hs + (size_t)r0 * F + sub * 8));
    }

    const float d = rsqrtf((float)deg + 1.0f);
    float4 bva = *(const float4*)(bias + sub * 8);
    float4 bvb = *(const float4*)(bias + sub * 8 + 4);
    float o[8];
#pragma unroll
    for (int j = 0; j < 8; j++) {
        float bj = (j < 4) ? ((const float*)&bva)[j] : ((const float*)&bvb)[j - 4];
        o[j] = (a0[j] + a1[j] + a2[j] + a3[j]) * d + bj;
        if (RELU) o[j] = fmaxf(o[j], 0.f);
    }

    if constexpr (sizeof(TOUT) == 2) {
        __half2 p[4];
#pragma unroll
        for (int j = 0; j < 4; j++) p[j] = __floats2half2_rn(o[2 * j], o[2 * j + 1]);
        *(uint4*)((__half*)out + (size_t)node * F + sub * 8) = *(uint4*)p;
    } else {
        float* op = (float*)out + (size_t)node * F + sub * 8;
        *(float4*)(op)     = make_float4(o[0], o[1], o[2], o[3]);
        *(float4*)(op + 4) = make_float4(o[4], o[5], o[6], o[7]);
    }
}

// ---------------------------------------------------------------------------
// Launch (single stream, sequential)
// ---------------------------------------------------------------------------
extern "C" void kernel_launch(void* const* d_in, const int* in_sizes, int n_in,
                              void* d_out, int out_size) {
    const float* x  = (const float*)d_in[0];
    const int*   ei = (const int*)d_in[1];
    const float* W1 = (const float*)d_in[2];
    const float* b1 = (const float*)d_in[3];
    const float* W2 = (const float*)d_in[4];
    const float* b2 = (const float*)d_in[5];
    float* out = (float*)d_out;

    const int* row = ei;
    const int* col = ei + EE;

    constexpr int SMEM1 = (64 * 136 + 128 * 136) * 2;  // 52,224 B (F=128)
    constexpr int SMEM2 = (64 * 136 + 128 * 72) * 2;   // 35,840 B (F=64)

    static __half *p_hs1 = nullptr, *p_hh = nullptr, *p_hs2 = nullptr,
                  *p_w1h = nullptr, *p_w2h = nullptr;
    static int *p_cnt = nullptr, *p_slots = nullptr;
    if (!p_hs1) {
        cudaGetSymbolAddress((void**)&p_hs1,   g_hs1);
        cudaGetSymbolAddress((void**)&p_hh,    g_hh);
        cudaGetSymbolAddress((void**)&p_hs2,   g_hs2);
        cudaGetSymbolAddress((void**)&p_cnt,   g_cnt);
        cudaGetSymbolAddress((void**)&p_slots, g_slots);
        cudaGetSymbolAddress((void**)&p_w1h,   g_w1h);
        cudaGetSymbolAddress((void**)&p_w2h,   g_w2h);
        cudaFuncSetAttribute((const void*)gemm_tc_kernel<128, float>,
                             cudaFuncAttributeMaxDynamicSharedMemorySize, SMEM1);
        cudaFuncSetAttribute((const void*)gemm_tc_kernel<64, __half>,
                             cudaFuncAttributeMaxDynamicSharedMemorySize, SMEM2);
    }

    const int GBLK = (NN + 63) / 64;       // 782

    // ---- one-shot W conversion ----
    {
        constexpr int NPAIR = (FIN * FHID + FHID * FOUT) / 2;
        wconv_kernel<<<(NPAIR + 255) / 256, 256>>>(W1, W2, p_w1h, p_w2h);
    }

    // ---- single-pass CSR build ----
    cudaMemsetAsync(p_cnt, 0, (size_t)NN * sizeof(int), 0);
    fill_direct_kernel<<<(EE + 255) / 256, 256>>>(row, col, p_cnt, p_slots, EE);

    // ---- layer 1: fp16 tensor GEMM (hs1 = (x@W1)*dis) ----
    gemm_tc_kernel<128, float><<<GBLK, 256, SMEM1>>>(x, p_w1h, p_hs1, p_cnt, NN);

    // ---- layer 1 aggregate -> h (fp16) ----
    {
        long long threads = (long long)NN * (FHID / 8);
        aggregate_kernel<128, true, __half><<<(int)((threads + 255) / 256), 256>>>(
            p_hs1, p_slots, p_cnt, b1, p_hh, NN);
    }

    // ---- layer 2: fp16 tensor GEMM (hs2 = (h@W2)*dis) ----
    gemm_tc_kernel<64, __half><<<GBLK, 256, SMEM2>>>(p_hh, p_w2h, p_hs2, p_cnt, NN);

    // ---- layer 2 aggregate -> d_out (fp32) ----
    {
        long long threads = (long long)NN * (FOUT / 8);
        aggregate_kernel<64, false, float><<<(int)((threads + 255) / 256), 256>>>(
            p_hs2, p_slots, p_cnt, b2, out, NN);
    }
}

// round 13
// speedup vs baseline: 1.4034x; 1.0483x over previous
#include <cuda_runtime.h>
#include <cuda_bf16.h>
#include <cuda_fp16.h>
#include <cstdint>

// Problem constants
#define NN   50000
#define EE   800000
#define FIN  128
#define FHID 128
#define FOUT 64
#define SLOTS 64   // max in-degree slots per node (Poisson(16): P(deg>=64) ~ 1e-20)

// ---------------------------------------------------------------------------
// Scratch (static __device__ arrays — no allocation allowed)
// ---------------------------------------------------------------------------
__device__ __half g_hs1[(size_t)NN * FHID];  // GEMM1 out: (x@W1)*dis, fp16
__device__ __half g_hh[(size_t)NN * FHID];   // h = relu(dis*sum + b1),  fp16
__device__ __half g_hs2[(size_t)NN * FOUT];  // GEMM2 out: (h@W2)*dis,  fp16
__device__ int    g_cnt[NN];                 // per-node edge count (atomic)
__device__ int    g_slots[(size_t)NN * SLOTS]; // direct-mapped CSR
__device__ __half g_w1h[FIN * FHID];
__device__ __half g_w2h[FHID * FOUT];

// ---------------------------------------------------------------------------
// PTX helpers
// ---------------------------------------------------------------------------
__device__ __forceinline__ uint32_t smem_u32(const void* p) {
    return (uint32_t)__cvta_generic_to_shared(p);
}

__device__ __forceinline__ void ldmat_x4(uint32_t& r0, uint32_t& r1, uint32_t& r2, uint32_t& r3,
                                         uint32_t addr) {
    asm volatile("ldmatrix.sync.aligned.m8n8.x4.shared.b16 {%0,%1,%2,%3}, [%4];"
                 : "=r"(r0), "=r"(r1), "=r"(r2), "=r"(r3) : "r"(addr));
}
__device__ __forceinline__ void ldmat_x4_t(uint32_t& r0, uint32_t& r1, uint32_t& r2, uint32_t& r3,
                                           uint32_t addr) {
    asm volatile("ldmatrix.sync.aligned.m8n8.x4.trans.shared.b16 {%0,%1,%2,%3}, [%4];"
                 : "=r"(r0), "=r"(r1), "=r"(r2), "=r"(r3) : "r"(addr));
}

__device__ __forceinline__ void mma_f16(float* d, const uint32_t* a, uint32_t b0, uint32_t b1) {
    asm volatile(
        "mma.sync.aligned.m16n8k16.row.col.f32.f16.f16.f32 "
        "{%0,%1,%2,%3}, {%4,%5,%6,%7}, {%8,%9}, {%0,%1,%2,%3};"
        : "+f"(d[0]), "+f"(d[1]), "+f"(d[2]), "+f"(d[3])
        : "r"(a[0]), "r"(a[1]), "r"(a[2]), "r"(a[3]), "r"(b0), "r"(b1));
}

// fp16x2 accumulate of one uint4 (8 halves) into 4 half2 accumulators
__device__ __forceinline__ void hacc4(__half2* a, uint4 raw) {
    const __half2* h = (const __half2*)&raw;
    a[0] = __hadd2(a[0], h[0]);
    a[1] = __hadd2(a[1], h[1]);
    a[2] = __hadd2(a[2], h[2]);
    a[3] = __hadd2(a[3], h[3]);
}

// ---------------------------------------------------------------------------
// One-shot W conversion fp32 -> fp16
// ---------------------------------------------------------------------------
__global__ void wconv_kernel(const float* __restrict__ W1, const float* __restrict__ W2,
                             __half* __restrict__ w1h, __half* __restrict__ w2h) {
    constexpr int N1 = (FIN * FHID) / 2;
    constexpr int N2 = (FHID * FOUT) / 2;
    int i = blockIdx.x * blockDim.x + threadIdx.x;
    if (i < N1) {
        float2 v = *(const float2*)(W1 + (size_t)i * 2);
        *(__half2*)(w1h + (size_t)i * 2) = __floats2half2_rn(v.x, v.y);
    } else if (i < N1 + N2) {
        int j = i - N1;
        float2 v = *(const float2*)(W2 + (size_t)j * 2);
        *(__half2*)(w2h + (size_t)j * 2) = __floats2half2_rn(v.x, v.y);
    }
}

// ---------------------------------------------------------------------------
// Single-pass CSR build: slot = cnt[col]++; slots[col*SLOTS + slot] = row
// ---------------------------------------------------------------------------
__global__ void fill_direct_kernel(const int* __restrict__ row, const int* __restrict__ col,
                                   int* __restrict__ cnt, int* __restrict__ slots, int e) {
    int i = blockIdx.x * blockDim.x + threadIdx.x;
    if (i < e) {
        int c = col[i];
        int s = atomicAdd(&cnt[c], 1);
        slots[(size_t)c * SLOTS + s] = row[i];
    }
}

// ---------------------------------------------------------------------------
// Tensor-core GEMM, fp16 inputs, FULL K (=128) resident in smem (1 barrier):
//   out[N, F] = (x[N, 128] @ W[128, F]) * rsqrt(cnt[row]+1),  out fp16.
// BM=64, 8 warps (warp = 16-row slab x F/2 cols).
// ---------------------------------------------------------------------------
template <int F, typename TIN>
__global__ void __launch_bounds__(256)
gemm_tc_kernel(const TIN* __restrict__ x,
               const __half* __restrict__ wg,
               __half* __restrict__ out, const int* __restrict__ cnt, int nrows) {
    constexpr int BM   = 64;
    constexpr int KT   = 128;
    constexpr int NT   = F / 16;
    constexpr int ASTR = KT + 8;
    constexpr int WSTR = F + 8;

    extern __shared__ __half smem[];
    __half* Ah = smem;
    __half* Wh = Ah + BM * ASTR;

    const int tid  = threadIdx.x;
    const int lane = tid & 31;
    const int w    = tid >> 5;
    const int slab = w >> 1;
    const int ch   = w & 1;
    const int row0 = blockIdx.x * BM;

    float acc[NT][4];
#pragma unroll
    for (int nt = 0; nt < NT; nt++)
#pragma unroll
        for (int j = 0; j < 4; j++) acc[nt][j] = 0.f;

    const int mat  = lane >> 3;
    const int mrow = lane & 7;

    if constexpr (sizeof(TIN) == 4) {
        constexpr int NV = (BM * KT) / 4;
#pragma unroll
        for (int p = tid; p < NV; p += 256) {
            int r  = p / (KT / 4);
            int kq = (p % (KT / 4)) * 4;
            float4 v;
            int grow = row0 + r;
            if (grow < nrows)
                v = *(const float4*)((const float*)x + (size_t)grow * FIN + kq);
            else
                v = make_float4(0.f, 0.f, 0.f, 0.f);
            *(__half2*)(Ah + r * ASTR + kq)     = __floats2half2_rn(v.x, v.y);
            *(__half2*)(Ah + r * ASTR + kq + 2) = __floats2half2_rn(v.z, v.w);
        }
    } else {
        constexpr int NV = (BM * KT) / 8;
#pragma unroll
        for (int p = tid; p < NV; p += 256) {
            int r  = p / (KT / 8);
            int kq = (p % (KT / 8)) * 8;
            uint4 v;
            int grow = row0 + r;
            if (grow < nrows)
                v = *(const uint4*)((const __half*)x + (size_t)grow * FIN + kq);
            else
                v = make_uint4(0, 0, 0, 0);
            *(uint4*)(Ah + r * ASTR + kq) = v;
        }
    }
    {
        constexpr int NV = (KT * F) / 8;
#pragma unroll
        for (int p = tid; p < NV; p += 256) {
            int k = p / (F / 8);
            int c = (p % (F / 8)) * 8;
            *(uint4*)(Wh + k * WSTR + c) = *(const uint4*)(wg + (size_t)k * F + c);
        }
    }
    __syncthreads();

#pragma unroll
    for (int ks = 0; ks < KT / 16; ks++) {
        uint32_t ah[4];
        {
            int arow = slab * 16 + (mat & 1) * 8 + mrow;
            int acol = ks * 16 + (mat >> 1) * 8;
            ldmat_x4(ah[0], ah[1], ah[2], ah[3], smem_u32(Ah + arow * ASTR + acol));
        }
#pragma unroll
        for (int nt2 = 0; nt2 < NT / 2; nt2++) {
            int krow = ks * 16 + (mat & 1) * 8 + mrow;
            int ncol = ch * (F / 2) + nt2 * 16 + (mat >> 1) * 8;
            uint32_t bh[4];
            ldmat_x4_t(bh[0], bh[1], bh[2], bh[3], smem_u32(Wh + krow * WSTR + ncol));
            mma_f16(acc[2 * nt2],     ah, bh[0], bh[1]);
            mma_f16(acc[2 * nt2 + 1], ah, bh[2], bh[3]);
        }
    }

    {
        int r0 = row0 + slab * 16 + (lane >> 2);
        int r1 = r0 + 8;
        float s0 = (r0 < nrows) ? rsqrtf((float)__ldg(cnt + r0) + 1.0f) : 0.f;
        float s1 = (r1 < nrows) ? rsqrtf((float)__ldg(cnt + r1) + 1.0f) : 0.f;
        int cbase = ch * (F / 2) + (lane & 3) * 2;
#pragma unroll
        for (int nt = 0; nt < NT; nt++) {
            int c = cbase + nt * 8;
            if (r0 < nrows)
                *(__half2*)(out + (size_t)r0 * F + c) = __floats2half2_rn(acc[nt][0] * s0, acc[nt][1] * s0);
            if (r1 < nrows)
                *(__half2*)(out + (size_t)r1 * F + c) = __floats2half2_rn(acc[nt][2] * s1, acc[nt][3] * s1);
        }
    }
}

// ---------------------------------------------------------------------------
// Segment-sum aggregate over fp16 features; fp16x2 (HADD2) accumulation in
// 4 independent ILP accumulators (chain length ~deg/4+1), fp32 final combine.
// Segment for node i = slots[i*SLOTS .. i*SLOTS + cnt[i]).
// ---------------------------------------------------------------------------
template <int F, bool RELU, typename TOUT>
__global__ void __launch_bounds__(256)
aggregate_kernel(const __half* __restrict__ hs,
                 const int* __restrict__ slots, const int* __restrict__ cnt,
                 const float* __restrict__ bias,
                 TOUT* __restrict__ out, int n) {
    constexpr int LPN = F / 8;
    const int gtid = blockIdx.x * blockDim.x + threadIdx.x;
    const int node = gtid / LPN;
    const int sub  = gtid % LPN;
    if (node >= n) return;

    const int deg = __ldg(cnt + node);
    const int beg = node * SLOTS;
    const int end = beg + deg;

    __half2 a0[4], a1[4], a2[4], a3[4];
    // self loop seeds a0; others zero
    {
        uint4 s = *(const uint4*)(hs + (size_t)node * F + sub * 8);
        const __half2* h = (const __half2*)&s;
        __half2 z = __floats2half2_rn(0.f, 0.f);
#pragma unroll
        for (int j = 0; j < 4; j++) { a0[j] = h[j]; a1[j] = z; a2[j] = z; a3[j] = z; }
    }

    int e = beg;
    for (; e + 3 < end; e += 4) {
        int r0 = __ldg(slots + e);
        int r1 = __ldg(slots + e + 1);
        int r2 = __ldg(slots + e + 2);
        int r3 = __ldg(slots + e + 3);
        uint4 v0 = *(const uint4*)(hs + (size_t)r0 * F + sub * 8);
        uint4 v1 = *(const uint4*)(hs + (size_t)r1 * F + sub * 8);
        uint4 v2 = *(const uint4*)(hs + (size_t)r2 * F + sub * 8);
        uint4 v3 = *(const uint4*)(hs + (size_t)r3 * F + sub * 8);
        hacc4(a0, v0); hacc4(a1, v1); hacc4(a2, v2); hacc4(a3, v3);
    }
    for (; e < end; e++) {
        int r0 = __ldg(slots + e);
        hacc4(a1, *(const uint4*)(hs + (size_t)r0 * F + sub * 8));
    }

    // fp32 final combine
    const float d = rsqrtf((float)deg + 1.0f);
    float4 bva = *(const float4*)(bias + sub * 8);
    float4 bvb = *(const float4*)(bias + sub * 8 + 4);
    float o[8];
#pragma unroll
    for (int j = 0; j < 4; j++) {
        float2 f0 = __half22float2(a0[j]);
        float2 f1 = __half22float2(a1[j]);
        float2 f2 = __half22float2(a2[j]);
        float2 f3 = __half22float2(a3[j]);
        o[2 * j]     = (f0.x + f1.x) + (f2.x + f3.x);
        o[2 * j + 1] = (f0.y + f1.y) + (f2.y + f3.y);
    }
#pragma unroll
    for (int j = 0; j < 8; j++) {
        float bj = (j < 4) ? ((const float*)&bva)[j] : ((const float*)&bvb)[j - 4];
        o[j] = o[j] * d + bj;
        if (RELU) o[j] = fmaxf(o[j], 0.f);
    }

    if constexpr (sizeof(TOUT) == 2) {
        __half2 p[4];
#pragma unroll
        for (int j = 0; j < 4; j++) p[j] = __floats2half2_rn(o[2 * j], o[2 * j + 1]);
        *(uint4*)((__half*)out + (size_t)node * F + sub * 8) = *(uint4*)p;
    } else {
        float* op = (float*)out + (size_t)node * F + sub * 8;
        *(float4*)(op)     = make_float4(o[0], o[1], o[2], o[3]);
        *(float4*)(op + 4) = make_float4(o[4], o[5], o[6], o[7]);
    }
}

// ---------------------------------------------------------------------------
// Launch: two-branch fork — side stream does memset+fill (L2-atomic bound),
// main stream does wconv+GEMM1 (tensor bound); join before aggregate1.
// ---------------------------------------------------------------------------
extern "C" void kernel_launch(void* const* d_in, const int* in_sizes, int n_in,
                              void* d_out, int out_size) {
    const float* x  = (const float*)d_in[0];
    const int*   ei = (const int*)d_in[1];
    const float* W1 = (const float*)d_in[2];
    const float* b1 = (const float*)d_in[3];
    const float* W2 = (const float*)d_in[4];
    const float* b2 = (const float*)d_in[5];
    float* out = (float*)d_out;

    const int* row = ei;
    const int* col = ei + EE;

    constexpr int SMEM1 = (64 * 136 + 128 * 136) * 2;  // 52,224 B (F=128)
    constexpr int SMEM2 = (64 * 136 + 128 * 72) * 2;   // 35,840 B (F=64)

    static __half *p_hs1 = nullptr, *p_hh = nullptr, *p_hs2 = nullptr,
                  *p_w1h = nullptr, *p_w2h = nullptr;
    static int *p_cnt = nullptr, *p_slots = nullptr;
    static cudaStream_t s_side = nullptr;
    static cudaEvent_t s_fork = nullptr, s_join = nullptr;
    if (!p_hs1) {
        cudaGetSymbolAddress((void**)&p_hs1,   g_hs1);
        cudaGetSymbolAddress((void**)&p_hh,    g_hh);
        cudaGetSymbolAddress((void**)&p_hs2,   g_hs2);
        cudaGetSymbolAddress((void**)&p_cnt,   g_cnt);
        cudaGetSymbolAddress((void**)&p_slots, g_slots);
        cudaGetSymbolAddress((void**)&p_w1h,   g_w1h);
        cudaGetSymbolAddress((void**)&p_w2h,   g_w2h);
        cudaFuncSetAttribute((const void*)gemm_tc_kernel<128, float>,
                             cudaFuncAttributeMaxDynamicSharedMemorySize, SMEM1);
        cudaFuncSetAttribute((const void*)gemm_tc_kernel<64, __half>,
                             cudaFuncAttributeMaxDynamicSharedMemorySize, SMEM2);
        cudaStreamCreateWithFlags(&s_side, cudaStreamNonBlocking);
        cudaEventCreateWithFlags(&s_fork, cudaEventDisableTiming);
        cudaEventCreateWithFlags(&s_join, cudaEventDisableTiming);
    }

    const int GBLK = (NN + 63) / 64;       // 782

    // ---- fork: CSR build on side stream ----
    cudaEventRecord(s_fork, 0);
    cudaStreamWaitEvent(s_side, s_fork, 0);
    cudaMemsetAsync(p_cnt, 0, (size_t)NN * sizeof(int), s_side);
    fill_direct_kernel<<<(EE + 255) / 256, 256, 0, s_side>>>(row, col, p_cnt, p_slots, EE);
    cudaEventRecord(s_join, s_side);

    // ---- main: W conversion + layer 1 GEMM ----
    {
        constexpr int NPAIR = (FIN * FHID + FHID * FOUT) / 2;
        wconv_kernel<<<(NPAIR + 255) / 256, 256>>>(W1, W2, p_w1h, p_w2h);
    }
    // NOTE: gemm1 epilogue reads cnt — it must wait for fill too.
    cudaStreamWaitEvent(0, s_join, 0);
    gemm_tc_kernel<128, float><<<GBLK, 256, SMEM1>>>(x, p_w1h, p_hs1, p_cnt, NN);

    // ---- layer 1 aggregate -> h (fp16) ----
    {
        long long threads = (long long)NN * (FHID / 8);
        aggregate_kernel<128, true, __half><<<(int)((threads + 255) / 256), 256>>>(
            p_hs1, p_slots, p_cnt, b1, p_hh, NN);
    }

    // ---- layer 2: fp16 tensor GEMM ----
    gemm_tc_kernel<64, __half><<<GBLK, 256, SMEM2>>>(p_hh, p_w2h, p_hs2, p_cnt, NN);

    // ---- layer 2 aggregate -> d_out (fp32) ----
    {
        long long threads = (long long)NN * (FOUT / 8);
        aggregate_kernel<64, false, float><<<(int)((threads + 255) / 256), 256>>>(
            p_hs2, p_slots, p_cnt, b2, out, NN);
    }
}